// round 14
// baseline (speedup 1.0000x reference)
#include <cuda_runtime.h>
#include <cuda_bf16.h>
#include <cstdint>

// ---------------------------------------------------------------------------
// Dual-EdgeConv (tpl/geo) + final MLP, fp32 math, mma.sync (HMMA) GEMMs.
//   layer1 factorized:  pre1 = P[dst] + B[src]
//   Stats pass stages split-bf16 h1 tile blobs to DRAM (g_h1stage);
//   the edge GEMM streams them back as contiguous 32KB copies (no gather).
//   BN1 fold inlined in the edge GEMM; BN2 fused into the final GEMM.
//   segment_max via row-coalesced LDG-filtered atomicMax.
// ---------------------------------------------------------------------------

static constexpr int NN   = 100000;
static constexpr int CIN  = 32;
static constexpr int HH   = 64;
static constexpr int COUT = 128;
static constexpr int EE   = 1000000;
static constexpr int MM   = EE + NN;
static constexpr int NTILES = (MM + 127) / 128;          // 8594
#define GCU_EPS 1e-5f

__device__ float    g_P[NN * HH];
__device__ float    g_B[NN * HH];
__device__ unsigned g_nodemax[2 * NN * HH];              // per-conv buffers
__device__ float    g_stats[2 * 4 * HH];                 // per-conv [S1|SS1|S2|SS2]
__device__ float    g_fstats[2 * COUT];
__device__ __align__(16) unsigned char g_h1stage[(size_t)NTILES * 32768];

__device__ __forceinline__ uint32_t smem_u32(const void* p) {
    uint32_t a;
    asm("{ .reg .u64 t; cvta.to.shared.u64 t, %1; cvt.u32.u64 %0, t; }" : "=r"(a) : "l"(p));
    return a;
}
__device__ __forceinline__ void ldm_x4(uint32_t* r, uint32_t addr) {
    asm volatile("ldmatrix.sync.aligned.m8n8.x4.shared.b16 {%0,%1,%2,%3}, [%4];"
                 : "=r"(r[0]), "=r"(r[1]), "=r"(r[2]), "=r"(r[3]) : "r"(addr));
}
__device__ __forceinline__ void mma16816(float* c, const uint32_t* a, const uint32_t* b) {
    asm volatile("mma.sync.aligned.m16n8k16.row.col.f32.bf16.bf16.f32 "
                 "{%0,%1,%2,%3}, {%4,%5,%6,%7}, {%8,%9}, {%0,%1,%2,%3};"
                 : "+f"(c[0]), "+f"(c[1]), "+f"(c[2]), "+f"(c[3])
                 : "r"(a[0]), "r"(a[1]), "r"(a[2]), "r"(a[3]), "r"(b[0]), "r"(b[1]));
}
__device__ __forceinline__ void split2(float x, float y, uint32_t& hi, uint32_t& lo) {
    __nv_bfloat162 h2 = __floats2bfloat162_rn(x, y);
    float2 hf = __bfloat1622float2(h2);
    __nv_bfloat162 l2 = __floats2bfloat162_rn(x - hf.x, y - hf.y);
    hi = *(uint32_t*)&h2;
    lo = *(uint32_t*)&l2;
}

// ---------------------------------------------------------------------------
__global__ __launch_bounds__(256) void k_clear() {
    int i  = blockIdx.x * blockDim.x + threadIdx.x;
    int st = gridDim.x * blockDim.x;
    for (int j = i; j < 2 * NN * HH; j += st) g_nodemax[j] = 0x80000000u;  // enc(0.0f)
    if (i < 2 * 4 * HH) g_stats[i] = 0.f;
    if (i < 2 * COUT) g_fstats[i] = 0.f;
}

// ---------------------------------------------------------------------------
__global__ __launch_bounds__(256) void k_precompute(const float* __restrict__ x,
                                                    const float* __restrict__ W1,
                                                    const float* __restrict__ b1) {
    __shared__ float Wp[CIN * HH];
    __shared__ float Wb[CIN * HH];
    __shared__ float b1s[HH];
    int t = threadIdx.x, lane = t & 31;
    for (int idx = t; idx < CIN * HH; idx += 256) {
        int c = idx >> 5, k = idx & 31;
        float wa = W1[c * 64 + k];
        float wb = W1[c * 64 + 32 + k];
        Wp[k * HH + c] = wa - wb;
        Wb[k * HH + c] = wb;
    }
    if (t < HH) b1s[t] = b1[t];
    __syncthreads();

    int gw = (blockIdx.x * 256 + t) >> 5;
    int nw = (gridDim.x * 256) >> 5;
    for (int n = gw; n < NN; n += nw) {
        float xv = x[n * CIN + lane];
        float ap  = b1s[lane], ap2 = b1s[lane + 32];
        float ab  = 0.f,       ab2 = 0.f;
#pragma unroll
        for (int k = 0; k < CIN; k++) {
            float xk = __shfl_sync(0xffffffffu, xv, k);
            ap  += xk * Wp[k * HH + lane];
            ap2 += xk * Wp[k * HH + 32 + lane];
            ab  += xk * Wb[k * HH + lane];
            ab2 += xk * Wb[k * HH + 32 + lane];
        }
        g_P[n * HH + lane]      = ap;
        g_P[n * HH + 32 + lane] = ap2;
        g_B[n * HH + lane]      = ab;
        g_B[n * HH + 32 + lane] = ab2;
    }
}

// ---------------------------------------------------------------------------
// BN1 stats + stage split-bf16 h1 tile blobs (A-tile smem layout, 32KB/tile).
// No intra-loop barriers: warps fully independent.
__global__ __launch_bounds__(256) void k_stats_stage(const int* __restrict__ src,
                                                     const int* __restrict__ dst,
                                                     int coff) {
    __shared__ float red[2 * HH];
    int t = threadIdx.x, lane = t & 31, w = t >> 5;
    float s0 = 0.f, q0 = 0.f, s1 = 0.f, q1 = 0.f;   // ch 2*lane, 2*lane+1

    for (int tile = blockIdx.x; tile < NTILES; tile += gridDim.x) {
        int e0 = tile * 128 + w * 16;
        int sI = 0, dI = -1;
        if (lane < 16) {
            int mye = e0 + lane;
            if (mye < EE)      { sI = __ldg(&src[mye]); dI = __ldg(&dst[mye]); }
            else if (mye < MM) { sI = dI = mye - EE; }
        }
        unsigned char* blob = g_h1stage + (size_t)tile * 32768;
#pragma unroll 4
        for (int e = 0; e < 16; e++) {
            int sE = __shfl_sync(0xffffffffu, sI, e);
            int dE = __shfl_sync(0xffffffffu, dI, e);
            int r  = w * 16 + e;
            float h0 = 0.f, h1 = 0.f;
            if (dE >= 0) {
                float2 p = *(const float2*)(g_P + (size_t)dE * HH + 2 * lane);
                float2 b = *(const float2*)(g_B + (size_t)sE * HH + 2 * lane);
                h0 = fmaxf(p.x + b.x, 0.f);
                h1 = fmaxf(p.y + b.y, 0.f);
            }
            uint32_t hiw, low;
            split2(h0, h1, hiw, low);
            int off = r * 128 + ((lane * 4) ^ ((r & 7) << 4));
            *(uint32_t*)(blob + off)         = hiw;
            *(uint32_t*)(blob + 16384 + off) = low;
            s0 += h0; q0 += h0 * h0;
            s1 += h1; q1 += h1 * h1;
        }
    }

    if (t < 2 * HH) red[t] = 0.f;
    __syncthreads();
    atomicAdd(&red[2 * lane], s0);
    atomicAdd(&red[2 * lane + 1], s1);
    atomicAdd(&red[HH + 2 * lane], q0);
    atomicAdd(&red[HH + 2 * lane + 1], q1);
    __syncthreads();
    if (t < HH) {
        atomicAdd(&g_stats[coff + t], red[t]);
        atomicAdd(&g_stats[coff + HH + t], red[HH + t]);
    }
}

// ---------------------------------------------------------------------------
// Edge GEMM: streams staged A-tile blobs, MMA, transpose epilogue.
// Dynamic smem: [sAbuf 32K | sWhi 8K | sWlo 8K] = 48K.
static constexpr int EG_SMEM = 32768 + 8192 + 8192;

__global__ __launch_bounds__(256, 3) void k_edge_gemm_mma(const int* __restrict__ dst,
                                                          const float* __restrict__ W2,
                                                          const float* __restrict__ b2,
                                                          const float* __restrict__ g1,
                                                          const float* __restrict__ be1,
                                                          int coff, int nmoff) {
    extern __shared__ __align__(16) unsigned char eg_sm[];
    unsigned char* sAbuf = eg_sm;                          // A hi|lo, aliased by h2s
    uint32_t* sWhi = (uint32_t*)(eg_sm + 32768);
    uint32_t* sWlo = (uint32_t*)(eg_sm + 32768 + 8192);
    __shared__ float aS[HH], dS[HH], b2s[HH];
    __shared__ int dsts[128];
    __shared__ float red[2 * HH];

    unsigned char* sAhi = sAbuf;
    unsigned char* sAlo = sAbuf + 16384;
    float* h2s = (float*)sAbuf;                            // [128][64] swizzled

    int t = threadIdx.x, lane = t & 31, w = t >> 5;
    int wrow = w & 3, wcol = w >> 2;
    int g  = lane >> 2;
    int tg = lane & 3;

    if (t < HH) {
        float mu  = g_stats[coff + t] * (1.f / (float)MM);
        float var = g_stats[coff + HH + t] * (1.f / (float)MM) - mu * mu;
        float av  = g1[t] * rsqrtf(var + GCU_EPS);
        aS[t] = av;
        dS[t] = be1[t] - mu * av;
    }
    __syncthreads();

    // W fragments (folded) into smem
    if (wrow == 0) {
#pragma unroll
        for (int nb = 0; nb < 4; nb++) {
#pragma unroll
            for (int kb = 0; kb < 4; kb++) {
                int o  = wcol * 32 + nb * 8 + g;
                int k0 = kb * 16 + tg * 2;
                float w00 = W2[o * 64 + k0]     * aS[k0];
                float w01 = W2[o * 64 + k0 + 1] * aS[k0 + 1];
                float w10 = W2[o * 64 + k0 + 8] * aS[k0 + 8];
                float w11 = W2[o * 64 + k0 + 9] * aS[k0 + 9];
                uint32_t h0, l0, h1, l1;
                split2(w00, w01, h0, l0);
                split2(w10, w11, h1, l1);
                int bidx = (((wcol * 4 + nb) * 4 + kb) * 32 + lane) * 2;
                sWhi[bidx]     = h0;  sWhi[bidx + 1] = h1;
                sWlo[bidx]     = l0;  sWlo[bidx + 1] = l1;
            }
        }
    }
    if (t < HH) {
        float bb = b2[t];
        for (int c = 0; c < HH; c++) bb += W2[t * 64 + c] * dS[c];
        b2s[t] = bb;
    }
    if (t < 2 * HH) red[t] = 0.f;

    uint32_t aHiBase = smem_u32(sAhi), aLoBase = smem_u32(sAlo);
    int sub = lane >> 3, rr = lane & 7;
    uint32_t addrA[2][4];
#pragma unroll
    for (int mb = 0; mb < 2; mb++)
#pragma unroll
        for (int kb = 0; kb < 4; kb++) {
            int r    = wrow * 32 + mb * 16 + (sub & 1) * 8 + rr;
            int colb = kb * 32 + (sub >> 1) * 16;
            addrA[mb][kb] = (uint32_t)(r * 128 + (colb ^ ((r & 7) << 4)));
        }

    float s0 = 0.f, q0 = 0.f, s1 = 0.f, q1 = 0.f;   // ch = lane, lane+32
    __syncthreads();
    float b2a = b2s[lane];
    float b2b = b2s[lane + 32];

    unsigned* nmBase = g_nodemax + nmoff;
    for (int tile = blockIdx.x; tile < NTILES; tile += gridDim.x) {
        __syncthreads();   // phase-5 of prev tile done: sAbuf/dsts free

        // ---- phase 2: stream staged blob + dst indices ----
        {
            const uint4* gsrc = (const uint4*)(g_h1stage + (size_t)tile * 32768);
            uint4* sdst = (uint4*)sAbuf;
#pragma unroll
            for (int i = 0; i < 8; i++)
                sdst[t + i * 256] = __ldg(&gsrc[t + i * 256]);
            if (lane < 16) {
                int mye = tile * 128 + w * 16 + lane;
                int dI = -1;
                if (mye < EE)      dI = __ldg(&dst[mye]);
                else if (mye < MM) dI = mye - EE;
                dsts[w * 16 + lane] = dI;
            }
        }
        __syncthreads();

        // ---- phase 3: MMA ----
        float acc[2][4][4];
#pragma unroll
        for (int mb = 0; mb < 2; mb++)
#pragma unroll
            for (int nb = 0; nb < 4; nb++)
#pragma unroll
                for (int j = 0; j < 4; j++) acc[mb][nb][j] = 0.f;

#pragma unroll
        for (int kb = 0; kb < 4; kb++) {
            uint32_t ahi[2][4], alo[2][4];
#pragma unroll
            for (int mb = 0; mb < 2; mb++) {
                ldm_x4(ahi[mb], aHiBase + addrA[mb][kb]);
                ldm_x4(alo[mb], aLoBase + addrA[mb][kb]);
            }
#pragma unroll
            for (int nb = 0; nb < 4; nb++) {
                int bidx = (((wcol * 4 + nb) * 4 + kb) * 32 + lane) * 2;
                uint2 wh = *(const uint2*)&sWhi[bidx];
                uint2 wl = *(const uint2*)&sWlo[bidx];
                uint32_t whi2[2] = { wh.x, wh.y };
                uint32_t wlo2[2] = { wl.x, wl.y };
#pragma unroll
                for (int mb = 0; mb < 2; mb++) {
                    mma16816(acc[mb][nb], ahi[mb], whi2);
                    mma16816(acc[mb][nb], alo[mb], whi2);
                    mma16816(acc[mb][nb], ahi[mb], wlo2);
                }
            }
        }
        __syncthreads();   // all ldmatrix reads done; sAbuf reusable as h2s

        // ---- phase 4: store raw acc to h2s (XOR-swizzled rows) ----
#pragma unroll
        for (int mb = 0; mb < 2; mb++) {
#pragma unroll
            for (int half = 0; half < 2; half++) {
                int r  = wrow * 32 + mb * 16 + half * 8 + g;
                int sw = (r & 7) << 3;
#pragma unroll
                for (int nb = 0; nb < 4; nb++) {
                    int ch = wcol * 32 + nb * 8 + tg * 2;
                    float2 v = make_float2(acc[mb][nb][half * 2], acc[mb][nb][half * 2 + 1]);
                    *(float2*)&h2s[r * 64 + (ch ^ sw)] = v;
                }
            }
        }
        __syncthreads();

        // ---- phase 5: row-coalesced filter + atomics + stats ----
        for (int i = 0; i < 16; i++) {
            int r = w * 16 + i;
            int d = dsts[r];
            if (d < 0) continue;
            int sw = (r & 7) << 3;
            float v0 = fmaxf(h2s[r * 64 + (lane ^ sw)] + b2a, 0.f);
            float v1 = fmaxf(h2s[r * 64 + ((lane + 32) ^ sw)] + b2b, 0.f);
            s0 += v0; q0 += v0 * v0;
            s1 += v1; q1 += v1 * v1;
            unsigned* nm = nmBase + (size_t)d * HH;
            unsigned c0 = __ldg(&nm[lane]);
            unsigned c1 = __ldg(&nm[lane + 32]);
            unsigned e0v = __float_as_uint(v0) | 0x80000000u;
            unsigned e1v = __float_as_uint(v1) | 0x80000000u;
            if (e0v > c0) atomicMax(&nm[lane], e0v);
            if (e1v > c1) atomicMax(&nm[lane + 32], e1v);
        }
    }

    __syncthreads();
    atomicAdd(&red[lane], s0);
    atomicAdd(&red[lane + 32], s1);
    atomicAdd(&red[HH + lane], q0);
    atomicAdd(&red[HH + lane + 32], q1);
    __syncthreads();
    if (t < HH) {
        atomicAdd(&g_stats[coff + 2 * HH + t], red[t]);
        atomicAdd(&g_stats[coff + 3 * HH + t], red[HH + t]);
    }
}

// ---------------------------------------------------------------------------
// Final MLP GEMM: reads nodemax directly, applies BN2 affine inline (chunk=conv).
static constexpr int FG_SMEM = 4 * 32768;

__global__ __launch_bounds__(256) void k_final_gemm_mma(const float* __restrict__ Wf,
                                                        const float* __restrict__ bf,
                                                        const float* __restrict__ g2a,
                                                        const float* __restrict__ be2a,
                                                        const float* __restrict__ g2b,
                                                        const float* __restrict__ be2b,
                                                        float* __restrict__ out) {
    extern __shared__ __align__(16) unsigned char sm[];
    unsigned char* sXhi = sm;
    unsigned char* sXlo = sm + 32768;
    uint32_t* sWhi = (uint32_t*)(sm + 65536);
    uint32_t* sWloF = (uint32_t*)(sm + 65536 + 32768);
    __shared__ float bsh[COUT];
    __shared__ float red[2 * COUT];
    __shared__ float sc2[COUT], sh2[COUT];

    int t = threadIdx.x, lane = t & 31, w = t >> 5;
    int wrow = w & 3, wcol = w >> 2;
    int g = lane >> 2, tg = lane & 3;

    if (t < COUT) {
        bsh[t] = bf[t];
        int conv = t >> 6, c = t & 63;
        float mu  = g_stats[conv * 4 * HH + 2 * HH + c] * (1.f / (float)MM);
        float var = g_stats[conv * 4 * HH + 3 * HH + c] * (1.f / (float)MM) - mu * mu;
        float gv  = conv ? g2b[c] : g2a[c];
        float bev = conv ? be2b[c] : be2a[c];
        float inv = rsqrtf(var + GCU_EPS) * gv;
        sc2[t] = inv;
        sh2[t] = bev - mu * inv;
    }
    red[t] = 0.f;

    for (int i = 0; i < 16; i++) {
        int set  = w * 16 + i;
        int swc  = set >> 6, snb = (set >> 3) & 7, skb = set & 7;
        int o    = swc * 64 + snb * 8 + g;
        int k0   = skb * 16 + tg * 2;
        const float* Wr = Wf + o * COUT + k0;
        uint32_t h0, l0, h1, l1;
        split2(Wr[0], Wr[1], h0, l0);
        split2(Wr[8], Wr[9], h1, l1);
        int bidx = (((swc * 8 + snb) * 8 + skb) * 32 + lane) * 2;
        sWhi[bidx]      = h0;  sWhi[bidx + 1]  = h1;
        sWloF[bidx]     = l0;  sWloF[bidx + 1] = l1;
    }
    __syncthreads();   // sc2/sh2 ready before staging

    int nbase = blockIdx.x * 128;
    for (int idx = t; idx < 128 * 64; idx += 256) {
        int r = idx >> 6, pp = idx & 63;
        int chunk = pp >> 5, p = pp & 31;
        int n = nbase + r;
        float vx = 0.f, vy = 0.f;
        if (n < NN) {
            uint2 mv = *(const uint2*)&g_nodemax[(size_t)chunk * NN * HH + n * HH + 2 * p];
            int ch = chunk * 64 + 2 * p;
            vx = __uint_as_float(mv.x & 0x7fffffffu) * sc2[ch]     + sh2[ch];
            vy = __uint_as_float(mv.y & 0x7fffffffu) * sc2[ch + 1] + sh2[ch + 1];
        }
        uint32_t hiw, low;
        split2(vx, vy, hiw, low);
        int off = chunk * 16384 + r * 128 + ((p * 4) ^ ((r & 7) << 4));
        *(uint32_t*)(sXhi + off) = hiw;
        *(uint32_t*)(sXlo + off) = low;
    }
    __syncthreads();

    float acc[2][8][4];
#pragma unroll
    for (int mb = 0; mb < 2; mb++)
#pragma unroll
        for (int nb = 0; nb < 8; nb++)
#pragma unroll
            for (int j = 0; j < 4; j++) acc[mb][nb][j] = 0.f;

    uint32_t xHiBase = smem_u32(sXhi), xLoBase = smem_u32(sXlo);
    int sub = lane >> 3, rr = lane & 7;
#pragma unroll
    for (int kb = 0; kb < 8; kb++) {
        int chunk = kb >> 2, kk = kb & 3;
        uint32_t ahi[2][4], alo[2][4];
#pragma unroll
        for (int mb = 0; mb < 2; mb++) {
            int r    = wrow * 32 + mb * 16 + (sub & 1) * 8 + rr;
            int colb = kk * 32 + (sub >> 1) * 16;
            uint32_t a = (uint32_t)(chunk * 16384 + r * 128 + (colb ^ ((r & 7) << 4)));
            ldm_x4(ahi[mb], xHiBase + a);
            ldm_x4(alo[mb], xLoBase + a);
        }
#pragma unroll
        for (int nb = 0; nb < 8; nb++) {
            int bidx = (((wcol * 8 + nb) * 8 + kb) * 32 + lane) * 2;
            uint2 wh = *(const uint2*)&sWhi[bidx];
            uint2 wl = *(const uint2*)&sWloF[bidx];
            uint32_t whi2[2] = { wh.x, wh.y };
            uint32_t wlo2[2] = { wl.x, wl.y };
#pragma unroll
            for (int mb = 0; mb < 2; mb++) {
                mma16816(acc[mb][nb], ahi[mb], whi2);
                mma16816(acc[mb][nb], alo[mb], whi2);
                mma16816(acc[mb][nb], ahi[mb], wlo2);
            }
        }
    }

    float ls[16], lq[16];
#pragma unroll
    for (int i = 0; i < 16; i++) { ls[i] = 0.f; lq[i] = 0.f; }
#pragma unroll
    for (int mb = 0; mb < 2; mb++) {
#pragma unroll
        for (int half = 0; half < 2; half++) {
            int n = nbase + wrow * 32 + mb * 16 + half * 8 + g;
            if (n >= NN) continue;
#pragma unroll
            for (int nb = 0; nb < 8; nb++) {
                int o = wcol * 64 + nb * 8 + tg * 2;
                float v0 = fmaxf(acc[mb][nb][half * 2]     + bsh[o],     0.f);
                float v1 = fmaxf(acc[mb][nb][half * 2 + 1] + bsh[o + 1], 0.f);
                out[n * COUT + o]     = v0;
                out[n * COUT + o + 1] = v1;
                ls[nb * 2]     += v0; lq[nb * 2]     += v0 * v0;
                ls[nb * 2 + 1] += v1; lq[nb * 2 + 1] += v1 * v1;
            }
        }
    }
#pragma unroll
    for (int i = 0; i < 16; i++) {
#pragma unroll
        for (int dlt = 16; dlt >= 4; dlt >>= 1) {
            ls[i] += __shfl_down_sync(0xffffffffu, ls[i], dlt);
            lq[i] += __shfl_down_sync(0xffffffffu, lq[i], dlt);
        }
    }
    if (lane < 4) {
#pragma unroll
        for (int nb = 0; nb < 8; nb++) {
            int o = wcol * 64 + nb * 8 + tg * 2;
            atomicAdd(&red[o],            ls[nb * 2]);
            atomicAdd(&red[o + 1],        ls[nb * 2 + 1]);
            atomicAdd(&red[COUT + o],     lq[nb * 2]);
            atomicAdd(&red[COUT + o + 1], lq[nb * 2 + 1]);
        }
    }
    __syncthreads();
    if (t < COUT) {
        atomicAdd(&g_fstats[t],        red[t]);
        atomicAdd(&g_fstats[COUT + t], red[COUT + t]);
    }
}

// ---------------------------------------------------------------------------
__global__ __launch_bounds__(256) void k_norm(const float* __restrict__ gf,
                                              const float* __restrict__ bef,
                                              float* __restrict__ out) {
    __shared__ float sc[COUT], sh[COUT];
    int t = threadIdx.x;
    if (t < COUT) {
        float mu  = g_fstats[t] * (1.f / (float)NN);
        float var = g_fstats[COUT + t] * (1.f / (float)NN) - mu * mu;
        float inv = rsqrtf(var + GCU_EPS) * gf[t];
        sc[t] = inv;
        sh[t] = bef[t] - mu * inv;
    }
    __syncthreads();
    int i = blockIdx.x * 256 + t, st = gridDim.x * 256;
    for (; i < NN * COUT; i += st) {
        int c = i & 127;
        out[i] = out[i] * sc[c] + sh[c];
    }
}

// ---------------------------------------------------------------------------
extern "C" void kernel_launch(void* const* d_in, const int* in_sizes, int n_in,
                              void* d_out, int out_size) {
    const float* x     = (const float*)d_in[0];
    const int*   tpl_e = (const int*)d_in[1];
    const int*   geo_e = (const int*)d_in[2];
    const float* prm[2][8];
    for (int c = 0; c < 2; c++)
        for (int k = 0; k < 8; k++)
            prm[c][k] = (const float*)d_in[3 + c * 8 + k];
    const float* mlp_W  = (const float*)d_in[19];
    const float* mlp_b  = (const float*)d_in[20];
    const float* mlp_g  = (const float*)d_in[21];
    const float* mlp_be = (const float*)d_in[22];
    float* out = (float*)d_out;

    static int attr_done = 0;
    if (!attr_done) {
        cudaFuncSetAttribute(k_final_gemm_mma,
                             cudaFuncAttributeMaxDynamicSharedMemorySize, FG_SMEM);
        cudaFuncSetAttribute(k_edge_gemm_mma,
                             cudaFuncAttributeMaxDynamicSharedMemorySize, EG_SMEM);
        attr_done = 1;
    }

    k_clear<<<2048, 256>>>();
    for (int conv = 0; conv < 2; conv++) {
        const int* ei = conv ? geo_e : tpl_e;
        k_precompute<<<1024, 256>>>(x, prm[conv][0], prm[conv][1]);
        k_stats_stage<<<2048, 256>>>(ei, ei + EE, conv * 4 * HH);
        k_edge_gemm_mma<<<444, 256, EG_SMEM>>>(ei + EE, prm[conv][4], prm[conv][5],
                                               prm[conv][2], prm[conv][3],
                                               conv * 4 * HH, conv * NN * HH);
    }
    k_final_gemm_mma<<<(NN + 127) / 128, 256, FG_SMEM>>>(
        mlp_W, mlp_b, prm[0][6], prm[0][7], prm[1][6], prm[1][7], out);
    k_norm<<<2048, 256>>>(mlp_g, mlp_be, out);
}

// round 15
// speedup vs baseline: 1.0628x; 1.0628x over previous
#include <cuda_runtime.h>
#include <cuda_bf16.h>
#include <cstdint>

// ---------------------------------------------------------------------------
// Dual-EdgeConv (tpl/geo) + final MLP, fp32 math, mma.sync (HMMA) GEMMs.
//   Edges counting-sorted by dst per conv (self loop = first slot of each run).
//   layer1 factorized:  pre1 = P[dst] + B[src]
//   BN1 fold inlined in the edge GEMM; BN2 fused into the final GEMM.
//   Edge epilogue: transpose + RUN-MERGED filtered atomicMax (sorted dsts).
// ---------------------------------------------------------------------------

static constexpr int NN   = 100000;
static constexpr int CIN  = 32;
static constexpr int HH   = 64;
static constexpr int COUT = 128;
static constexpr int EE   = 1000000;
static constexpr int MM   = EE + NN;
static constexpr int NTILES = (MM + 127) / 128;
static constexpr int NBLK = (NN + 2047) / 2048;          // 49 scan blocks
#define GCU_EPS 1e-5f

__device__ float    g_P[NN * HH];
__device__ float    g_B[NN * HH];
__device__ unsigned g_nodemax[2 * NN * HH];
__device__ float    g_stats[2 * 4 * HH];
__device__ float    g_fstats[2 * COUT];
__device__ int      g_cnt[NN];
__device__ int      g_bsum[64];
__device__ int      g_cur[NN];
__device__ int      g_srcS[MM];
__device__ int      g_dstS[MM];

__device__ __forceinline__ uint32_t smem_u32(const void* p) {
    uint32_t a;
    asm("{ .reg .u64 t; cvta.to.shared.u64 t, %1; cvt.u32.u64 %0, t; }" : "=r"(a) : "l"(p));
    return a;
}
__device__ __forceinline__ void ldm_x4(uint32_t* r, uint32_t addr) {
    asm volatile("ldmatrix.sync.aligned.m8n8.x4.shared.b16 {%0,%1,%2,%3}, [%4];"
                 : "=r"(r[0]), "=r"(r[1]), "=r"(r[2]), "=r"(r[3]) : "r"(addr));
}
__device__ __forceinline__ void mma16816(float* c, const uint32_t* a, const uint32_t* b) {
    asm volatile("mma.sync.aligned.m16n8k16.row.col.f32.bf16.bf16.f32 "
                 "{%0,%1,%2,%3}, {%4,%5,%6,%7}, {%8,%9}, {%0,%1,%2,%3};"
                 : "+f"(c[0]), "+f"(c[1]), "+f"(c[2]), "+f"(c[3])
                 : "r"(a[0]), "r"(a[1]), "r"(a[2]), "r"(a[3]), "r"(b[0]), "r"(b[1]));
}
__device__ __forceinline__ void split2(float x, float y, uint32_t& hi, uint32_t& lo) {
    __nv_bfloat162 h2 = __floats2bfloat162_rn(x, y);
    float2 hf = __bfloat1622float2(h2);
    __nv_bfloat162 l2 = __floats2bfloat162_rn(x - hf.x, y - hf.y);
    hi = *(uint32_t*)&h2;
    lo = *(uint32_t*)&l2;
}

// ---------------------------------------------------------------------------
__global__ __launch_bounds__(256) void k_clear() {
    int i  = blockIdx.x * blockDim.x + threadIdx.x;
    int st = gridDim.x * blockDim.x;
    for (int j = i; j < 2 * NN * HH; j += st) g_nodemax[j] = 0x80000000u;  // enc(0.0f)
    if (i < 2 * 4 * HH) g_stats[i] = 0.f;
    if (i < 2 * COUT) g_fstats[i] = 0.f;
}

// ---------------- counting sort by dst -------------------------------------
__global__ __launch_bounds__(256) void k_hist_init() {
    int i  = blockIdx.x * blockDim.x + threadIdx.x;
    int st = gridDim.x * blockDim.x;
    for (int n = i; n < NN; n += st) g_cnt[n] = 1;       // self loop
    if (i < 64) g_bsum[i] = 0;
}
__global__ __launch_bounds__(256) void k_hist_count(const int* __restrict__ dst) {
    int i  = blockIdx.x * blockDim.x + threadIdx.x;
    int st = gridDim.x * blockDim.x;
    for (int e = i; e < EE; e += st) atomicAdd(&g_cnt[__ldg(&dst[e])], 1);
}
__global__ __launch_bounds__(256) void k_scanA() {
    int b = blockIdx.x, t = threadIdx.x, lane = t & 31;
    int base = b * 2048 + t * 8;
    int s = 0;
#pragma unroll
    for (int j = 0; j < 8; j++) {
        int i = base + j;
        if (i < NN) s += g_cnt[i];
    }
#pragma unroll
    for (int d = 16; d > 0; d >>= 1) s += __shfl_down_sync(0xffffffffu, s, d);
    if (lane == 0) atomicAdd(&g_bsum[b], s);
}
__global__ void k_scanB() {
    if (threadIdx.x == 0) {
        int run = 0;
        for (int i = 0; i < NBLK; i++) {
            int v = g_bsum[i];
            g_bsum[i] = run;
            run += v;
        }
    }
}
__global__ __launch_bounds__(256) void k_scanC() {
    __shared__ int tsum[256];
    int b = blockIdx.x, t = threadIdx.x;
    int base = b * 2048 + t * 8;
    int c[8];
    int s = 0;
#pragma unroll
    for (int j = 0; j < 8; j++) {
        int i = base + j;
        c[j] = (i < NN) ? g_cnt[i] : 0;
        s += c[j];
    }
    tsum[t] = s;
    __syncthreads();
    if (t == 0) {
        int run = 0;
        for (int j = 0; j < 256; j++) {
            int v = tsum[j];
            tsum[j] = run;
            run += v;
        }
    }
    __syncthreads();
    int pos = g_bsum[b] + tsum[t];
#pragma unroll
    for (int j = 0; j < 8; j++) {
        int i = base + j;
        if (i < NN) {
            g_cur[i]  = pos + 1;     // slot pos = self loop
            g_srcS[pos] = i;
            g_dstS[pos] = i;
            pos += c[j];
        }
    }
}
__global__ __launch_bounds__(256) void k_scatter(const int* __restrict__ src,
                                                 const int* __restrict__ dst) {
    int i  = blockIdx.x * blockDim.x + threadIdx.x;
    int st = gridDim.x * blockDim.x;
    for (int e = i; e < EE; e += st) {
        int d = __ldg(&dst[e]);
        int pos = atomicAdd(&g_cur[d], 1);
        g_srcS[pos] = __ldg(&src[e]);
        g_dstS[pos] = d;
    }
}

// ---------------------------------------------------------------------------
__global__ __launch_bounds__(256) void k_precompute(const float* __restrict__ x,
                                                    const float* __restrict__ W1,
                                                    const float* __restrict__ b1) {
    __shared__ float Wp[CIN * HH];
    __shared__ float Wb[CIN * HH];
    __shared__ float b1s[HH];
    int t = threadIdx.x, lane = t & 31;
    for (int idx = t; idx < CIN * HH; idx += 256) {
        int c = idx >> 5, k = idx & 31;
        float wa = W1[c * 64 + k];
        float wb = W1[c * 64 + 32 + k];
        Wp[k * HH + c] = wa - wb;
        Wb[k * HH + c] = wb;
    }
    if (t < HH) b1s[t] = b1[t];
    __syncthreads();

    int gw = (blockIdx.x * 256 + t) >> 5;
    int nw = (gridDim.x * 256) >> 5;
    for (int n = gw; n < NN; n += nw) {
        float xv = x[n * CIN + lane];
        float ap  = b1s[lane], ap2 = b1s[lane + 32];
        float ab  = 0.f,       ab2 = 0.f;
#pragma unroll
        for (int k = 0; k < CIN; k++) {
            float xk = __shfl_sync(0xffffffffu, xv, k);
            ap  += xk * Wp[k * HH + lane];
            ap2 += xk * Wp[k * HH + 32 + lane];
            ab  += xk * Wb[k * HH + lane];
            ab2 += xk * Wb[k * HH + 32 + lane];
        }
        g_P[n * HH + lane]      = ap;
        g_P[n * HH + 32 + lane] = ap2;
        g_B[n * HH + lane]      = ab;
        g_B[n * HH + 32 + lane] = ab2;
    }
}

// ---------------------------------------------------------------------------
// BN1 stats over sorted edges, 2 edges per warp-iteration (high MLP).
__global__ __launch_bounds__(256) void k_edge_stats(int coff) {
    __shared__ float red[2 * HH];
    int t = threadIdx.x, lane = t & 31;
    int gw = (blockIdx.x * 256 + t) >> 5;
    int nw = (gridDim.x * 256) >> 5;
    float s0 = 0.f, q0 = 0.f, s1 = 0.f, q1 = 0.f;
    for (int e = gw; e < MM; e += 2 * nw) {
        int e2 = e + nw;
        int sA = __ldg(&g_srcS[e]), dA = __ldg(&g_dstS[e]);
        bool v2 = (e2 < MM);
        int sB = 0, dB = 0;
        if (v2) { sB = __ldg(&g_srcS[e2]); dB = __ldg(&g_dstS[e2]); }
        float pa0 = __ldg(&g_P[dA * HH + lane]);
        float pa1 = __ldg(&g_P[dA * HH + 32 + lane]);
        float ba0 = __ldg(&g_B[sA * HH + lane]);
        float ba1 = __ldg(&g_B[sA * HH + 32 + lane]);
        float pb0 = 0.f, pb1 = 0.f, bb0 = 0.f, bb1 = 0.f;
        if (v2) {
            pb0 = __ldg(&g_P[dB * HH + lane]);
            pb1 = __ldg(&g_P[dB * HH + 32 + lane]);
            bb0 = __ldg(&g_B[sB * HH + lane]);
            bb1 = __ldg(&g_B[sB * HH + 32 + lane]);
        }
        float h0 = fmaxf(pa0 + ba0, 0.f);
        float h1 = fmaxf(pa1 + ba1, 0.f);
        s0 += h0; q0 += h0 * h0;
        s1 += h1; q1 += h1 * h1;
        if (v2) {
            float g0 = fmaxf(pb0 + bb0, 0.f);
            float g1 = fmaxf(pb1 + bb1, 0.f);
            s0 += g0; q0 += g0 * g0;
            s1 += g1; q1 += g1 * g1;
        }
    }
    if (t < 2 * HH) red[t] = 0.f;
    __syncthreads();
    atomicAdd(&red[lane], s0);
    atomicAdd(&red[lane + 32], s1);
    atomicAdd(&red[HH + lane], q0);
    atomicAdd(&red[HH + lane + 32], q1);
    __syncthreads();
    if (t < HH) {
        atomicAdd(&g_stats[coff + t], red[t]);
        atomicAdd(&g_stats[coff + HH + t], red[HH + t]);
    }
}

// ---------------------------------------------------------------------------
// Edge GEMM on sorted edges: gather, MMA, transpose + run-merged epilogue.
static constexpr int EG_SMEM = 32768 + 8192 + 8192;

__global__ __launch_bounds__(256, 3) void k_edge_gemm_mma(const float* __restrict__ W2,
                                                          const float* __restrict__ b2,
                                                          const float* __restrict__ g1,
                                                          const float* __restrict__ be1,
                                                          int coff, int nmoff) {
    extern __shared__ __align__(16) unsigned char eg_sm[];
    unsigned char* sAbuf = eg_sm;
    uint32_t* sWhi = (uint32_t*)(eg_sm + 32768);
    uint32_t* sWlo = (uint32_t*)(eg_sm + 32768 + 8192);
    __shared__ float aS[HH], dS[HH], b2s[HH];
    __shared__ int dsts[128];
    __shared__ float red[2 * HH];

    unsigned char* sAhi = sAbuf;
    unsigned char* sAlo = sAbuf + 16384;
    float* h2s = (float*)sAbuf;

    int t = threadIdx.x, lane = t & 31, w = t >> 5;
    int wrow = w & 3, wcol = w >> 2;
    int g  = lane >> 2;
    int tg = lane & 3;

    if (t < HH) {
        float mu  = g_stats[coff + t] * (1.f / (float)MM);
        float var = g_stats[coff + HH + t] * (1.f / (float)MM) - mu * mu;
        float av  = g1[t] * rsqrtf(var + GCU_EPS);
        aS[t] = av;
        dS[t] = be1[t] - mu * av;
    }
    __syncthreads();

    if (wrow == 0) {
#pragma unroll
        for (int nb = 0; nb < 4; nb++) {
#pragma unroll
            for (int kb = 0; kb < 4; kb++) {
                int o  = wcol * 32 + nb * 8 + g;
                int k0 = kb * 16 + tg * 2;
                float w00 = W2[o * 64 + k0]     * aS[k0];
                float w01 = W2[o * 64 + k0 + 1] * aS[k0 + 1];
                float w10 = W2[o * 64 + k0 + 8] * aS[k0 + 8];
                float w11 = W2[o * 64 + k0 + 9] * aS[k0 + 9];
                uint32_t h0, l0, h1, l1;
                split2(w00, w01, h0, l0);
                split2(w10, w11, h1, l1);
                int bidx = (((wcol * 4 + nb) * 4 + kb) * 32 + lane) * 2;
                sWhi[bidx]     = h0;  sWhi[bidx + 1] = h1;
                sWlo[bidx]     = l0;  sWlo[bidx + 1] = l1;
            }
        }
    }
    if (t < HH) {
        float bb = b2[t];
        for (int c = 0; c < HH; c++) bb += W2[t * 64 + c] * dS[c];
        b2s[t] = bb;
    }
    if (t < 2 * HH) red[t] = 0.f;

    uint32_t aHiBase = smem_u32(sAhi), aLoBase = smem_u32(sAlo);
    int sub = lane >> 3, rr = lane & 7;
    uint32_t addrA[2][4];
#pragma unroll
    for (int mb = 0; mb < 2; mb++)
#pragma unroll
        for (int kb = 0; kb < 4; kb++) {
            int r    = wrow * 32 + mb * 16 + (sub & 1) * 8 + rr;
            int colb = kb * 32 + (sub >> 1) * 16;
            addrA[mb][kb] = (uint32_t)(r * 128 + (colb ^ ((r & 7) << 4)));
        }

    float s0 = 0.f, q0 = 0.f, s1 = 0.f, q1 = 0.f;
    __syncthreads();
    float b2a = b2s[lane];
    float b2b = b2s[lane + 32];

    unsigned* nmBase = g_nodemax + nmoff;
    for (int tile = blockIdx.x; tile < NTILES; tile += gridDim.x) {
        __syncthreads();

        // ---- gather (sorted: dst run-coherent) ----
        int sI = 0, dI = -1;
        if (lane < 16) {
            int mye = tile * 128 + w * 16 + lane;
            if (mye < MM) { sI = __ldg(&g_srcS[mye]); dI = __ldg(&g_dstS[mye]); }
            dsts[w * 16 + lane] = dI;
        }
#pragma unroll 8
        for (int e = 0; e < 16; e++) {
            int sE = __shfl_sync(0xffffffffu, sI, e);
            int dE = __shfl_sync(0xffffffffu, dI, e);
            int r  = w * 16 + e;
            float h0 = 0.f, h1 = 0.f;
            if (dE >= 0) {
                float2 p = *(const float2*)(g_P + (size_t)dE * HH + 2 * lane);
                float2 b = *(const float2*)(g_B + (size_t)sE * HH + 2 * lane);
                h0 = fmaxf(p.x + b.x, 0.f);
                h1 = fmaxf(p.y + b.y, 0.f);
            }
            uint32_t hiw, low;
            split2(h0, h1, hiw, low);
            int off = r * 128 + ((lane * 4) ^ ((r & 7) << 4));
            *(uint32_t*)(sAhi + off) = hiw;
            *(uint32_t*)(sAlo + off) = low;
        }
        __syncthreads();

        // ---- MMA ----
        float acc[2][4][4];
#pragma unroll
        for (int mb = 0; mb < 2; mb++)
#pragma unroll
            for (int nb = 0; nb < 4; nb++)
#pragma unroll
                for (int j = 0; j < 4; j++) acc[mb][nb][j] = 0.f;

#pragma unroll
        for (int kb = 0; kb < 4; kb++) {
            uint32_t ahi[2][4], alo[2][4];
#pragma unroll
            for (int mb = 0; mb < 2; mb++) {
                ldm_x4(ahi[mb], aHiBase + addrA[mb][kb]);
                ldm_x4(alo[mb], aLoBase + addrA[mb][kb]);
            }
#pragma unroll
            for (int nb = 0; nb < 4; nb++) {
                int bidx = (((wcol * 4 + nb) * 4 + kb) * 32 + lane) * 2;
                uint2 wh = *(const uint2*)&sWhi[bidx];
                uint2 wl = *(const uint2*)&sWlo[bidx];
                uint32_t whi2[2] = { wh.x, wh.y };
                uint32_t wlo2[2] = { wl.x, wl.y };
#pragma unroll
                for (int mb = 0; mb < 2; mb++) {
                    mma16816(acc[mb][nb], ahi[mb], whi2);
                    mma16816(acc[mb][nb], alo[mb], whi2);
                    mma16816(acc[mb][nb], ahi[mb], wlo2);
                }
            }
        }
        __syncthreads();

        // ---- transpose store ----
#pragma unroll
        for (int mb = 0; mb < 2; mb++) {
#pragma unroll
            for (int half = 0; half < 2; half++) {
                int r  = wrow * 32 + mb * 16 + half * 8 + g;
                int sw = (r & 7) << 3;
#pragma unroll
                for (int nb = 0; nb < 4; nb++) {
                    int ch = wcol * 32 + nb * 8 + tg * 2;
                    float2 v = make_float2(acc[mb][nb][half * 2], acc[mb][nb][half * 2 + 1]);
                    *(float2*)&h2s[r * 64 + (ch ^ sw)] = v;
                }
            }
        }
        __syncthreads();

        // ---- run-merged filtered atomicMax + stats ----
        {
            int prevd = -1;
            float m0 = 0.f, m1 = 0.f;
            for (int i = 0; i < 16; i++) {
                int r = w * 16 + i;
                int d = dsts[r];
                if (d < 0) continue;           // pads only at global tail
                int sw = (r & 7) << 3;
                float v0 = fmaxf(h2s[r * 64 + (lane ^ sw)] + b2a, 0.f);
                float v1 = fmaxf(h2s[r * 64 + ((lane + 32) ^ sw)] + b2b, 0.f);
                s0 += v0; q0 += v0 * v0;
                s1 += v1; q1 += v1 * v1;
                if (d != prevd) {
                    if (prevd >= 0) {
                        unsigned* nm = nmBase + (size_t)prevd * HH;
                        unsigned c0 = __ldg(&nm[lane]);
                        unsigned c1 = __ldg(&nm[lane + 32]);
                        unsigned e0v = __float_as_uint(m0) | 0x80000000u;
                        unsigned e1v = __float_as_uint(m1) | 0x80000000u;
                        if (e0v > c0) atomicMax(&nm[lane], e0v);
                        if (e1v > c1) atomicMax(&nm[lane + 32], e1v);
                    }
                    prevd = d;
                    m0 = v0;
                    m1 = v1;
                } else {
                    m0 = fmaxf(m0, v0);
                    m1 = fmaxf(m1, v1);
                }
            }
            if (prevd >= 0) {
                unsigned* nm = nmBase + (size_t)prevd * HH;
                unsigned c0 = __ldg(&nm[lane]);
                unsigned c1 = __ldg(&nm[lane + 32]);
                unsigned e0v = __float_as_uint(m0) | 0x80000000u;
                unsigned e1v = __float_as_uint(m1) | 0x80000000u;
                if (e0v > c0) atomicMax(&nm[lane], e0v);
                if (e1v > c1) atomicMax(&nm[lane + 32], e1v);
            }
        }
    }

    __syncthreads();
    atomicAdd(&red[lane], s0);
    atomicAdd(&red[lane + 32], s1);
    atomicAdd(&red[HH + lane], q0);
    atomicAdd(&red[HH + lane + 32], q1);
    __syncthreads();
    if (t < HH) {
        atomicAdd(&g_stats[coff + 2 * HH + t], red[t]);
        atomicAdd(&g_stats[coff + 3 * HH + t], red[HH + t]);
    }
}

// ---------------------------------------------------------------------------
// Final MLP GEMM: reads nodemax directly, applies BN2 affine inline.
static constexpr int FG_SMEM = 4 * 32768;

__global__ __launch_bounds__(256) void k_final_gemm_mma(const float* __restrict__ Wf,
                                                        const float* __restrict__ bf,
                                                        const float* __restrict__ g2a,
                                                        const float* __restrict__ be2a,
                                                        const float* __restrict__ g2b,
                                                        const float* __restrict__ be2b,
                                                        float* __restrict__ out) {
    extern __shared__ __align__(16) unsigned char sm[];
    unsigned char* sXhi = sm;
    unsigned char* sXlo = sm + 32768;
    uint32_t* sWhi = (uint32_t*)(sm + 65536);
    uint32_t* sWloF = (uint32_t*)(sm + 65536 + 32768);
    __shared__ float bsh[COUT];
    __shared__ float red[2 * COUT];
    __shared__ float sc2[COUT], sh2[COUT];

    int t = threadIdx.x, lane = t & 31, w = t >> 5;
    int wrow = w & 3, wcol = w >> 2;
    int g = lane >> 2, tg = lane & 3;

    if (t < COUT) {
        bsh[t] = bf[t];
        int conv = t >> 6, c = t & 63;
        float mu  = g_stats[conv * 4 * HH + 2 * HH + c] * (1.f / (float)MM);
        float var = g_stats[conv * 4 * HH + 3 * HH + c] * (1.f / (float)MM) - mu * mu;
        float gv  = conv ? g2b[c] : g2a[c];
        float bev = conv ? be2b[c] : be2a[c];
        float inv = rsqrtf(var + GCU_EPS) * gv;
        sc2[t] = inv;
        sh2[t] = bev - mu * inv;
    }
    red[t] = 0.f;

    for (int i = 0; i < 16; i++) {
        int set  = w * 16 + i;
        int swc  = set >> 6, snb = (set >> 3) & 7, skb = set & 7;
        int o    = swc * 64 + snb * 8 + g;
        int k0   = skb * 16 + tg * 2;
        const float* Wr = Wf + o * COUT + k0;
        uint32_t h0, l0, h1, l1;
        split2(Wr[0], Wr[1], h0, l0);
        split2(Wr[8], Wr[9], h1, l1);
        int bidx = (((swc * 8 + snb) * 8 + skb) * 32 + lane) * 2;
        sWhi[bidx]      = h0;  sWhi[bidx + 1]  = h1;
        sWloF[bidx]     = l0;  sWloF[bidx + 1] = l1;
    }
    __syncthreads();

    int nbase = blockIdx.x * 128;
    for (int idx = t; idx < 128 * 64; idx += 256) {
        int r = idx >> 6, pp = idx & 63;
        int chunk = pp >> 5, p = pp & 31;
        int n = nbase + r;
        float vx = 0.f, vy = 0.f;
        if (n < NN) {
            uint2 mv = *(const uint2*)&g_nodemax[(size_t)chunk * NN * HH + n * HH + 2 * p];
            int ch = chunk * 64 + 2 * p;
            vx = __uint_as_float(mv.x & 0x7fffffffu) * sc2[ch]     + sh2[ch];
            vy = __uint_as_float(mv.y & 0x7fffffffu) * sc2[ch + 1] + sh2[ch + 1];
        }
        uint32_t hiw, low;
        split2(vx, vy, hiw, low);
        int off = chunk * 16384 + r * 128 + ((p * 4) ^ ((r & 7) << 4));
        *(uint32_t*)(sXhi + off) = hiw;
        *(uint32_t*)(sXlo + off) = low;
    }
    __syncthreads();

    float acc[2][8][4];
#pragma unroll
    for (int mb = 0; mb < 2; mb++)
#pragma unroll
        for (int nb = 0; nb < 8; nb++)
#pragma unroll
            for (int j = 0; j < 4; j++) acc[mb][nb][j] = 0.f;

    uint32_t xHiBase = smem_u32(sXhi), xLoBase = smem_u32(sXlo);
    int sub = lane >> 3, rr = lane & 7;
#pragma unroll
    for (int kb = 0; kb < 8; kb++) {
        int chunk = kb >> 2, kk = kb & 3;
        uint32_t ahi[2][4], alo[2][4];
#pragma unroll
        for (int mb = 0; mb < 2; mb++) {
            int r    = wrow * 32 + mb * 16 + (sub & 1) * 8 + rr;
            int colb = kk * 32 + (sub >> 1) * 16;
            uint32_t a = (uint32_t)(chunk * 16384 + r * 128 + (colb ^ ((r & 7) << 4)));
            ldm_x4(ahi[mb], xHiBase + a);
            ldm_x4(alo[mb], xLoBase + a);
        }
#pragma unroll
        for (int nb = 0; nb < 8; nb++) {
            int bidx = (((wcol * 8 + nb) * 8 + kb) * 32 + lane) * 2;
            uint2 wh = *(const uint2*)&sWhi[bidx];
            uint2 wl = *(const uint2*)&sWloF[bidx];
            uint32_t whi2[2] = { wh.x, wh.y };
            uint32_t wlo2[2] = { wl.x, wl.y };
#pragma unroll
            for (int mb = 0; mb < 2; mb++) {
                mma16816(acc[mb][nb], ahi[mb], whi2);
                mma16816(acc[mb][nb], alo[mb], whi2);
                mma16816(acc[mb][nb], ahi[mb], wlo2);
            }
        }
    }

    float ls[16], lq[16];
#pragma unroll
    for (int i = 0; i < 16; i++) { ls[i] = 0.f; lq[i] = 0.f; }
#pragma unroll
    for (int mb = 0; mb < 2; mb++) {
#pragma unroll
        for (int half = 0; half < 2; half++) {
            int n = nbase + wrow * 32 + mb * 16 + half * 8 + g;
            if (n >= NN) continue;
#pragma unroll
            for (int nb = 0; nb < 8; nb++) {
                int o = wcol * 64 + nb * 8 + tg * 2;
                float v0 = fmaxf(acc[mb][nb][half * 2]     + bsh[o],     0.f);
                float v1 = fmaxf(acc[mb][nb][half * 2 + 1] + bsh[o + 1], 0.f);
                out[n * COUT + o]     = v0;
                out[n * COUT + o + 1] = v1;
                ls[nb * 2]     += v0; lq[nb * 2]     += v0 * v0;
                ls[nb * 2 + 1] += v1; lq[nb * 2 + 1] += v1 * v1;
            }
        }
    }
#pragma unroll
    for (int i = 0; i < 16; i++) {
#pragma unroll
        for (int dlt = 16; dlt >= 4; dlt >>= 1) {
            ls[i] += __shfl_down_sync(0xffffffffu, ls[i], dlt);
            lq[i] += __shfl_down_sync(0xffffffffu, lq[i], dlt);
        }
    }
    if (lane < 4) {
#pragma unroll
        for (int nb = 0; nb < 8; nb++) {
            int o = wcol * 64 + nb * 8 + tg * 2;
            atomicAdd(&red[o],            ls[nb * 2]);
            atomicAdd(&red[o + 1],        ls[nb * 2 + 1]);
            atomicAdd(&red[COUT + o],     lq[nb * 2]);
            atomicAdd(&red[COUT + o + 1], lq[nb * 2 + 1]);
        }
    }
    __syncthreads();
    if (t < COUT) {
        atomicAdd(&g_fstats[t],        red[t]);
        atomicAdd(&g_fstats[COUT + t], red[COUT + t]);
    }
}

// ---------------------------------------------------------------------------
__global__ __launch_bounds__(256) void k_norm(const float* __restrict__ gf,
                                              const float* __restrict__ bef,
                                              float* __restrict__ out) {
    __shared__ float sc[COUT], sh[COUT];
    int t = threadIdx.x;
    if (t < COUT) {
        float mu  = g_fstats[t] * (1.f / (float)NN);
        float var = g_fstats[COUT + t] * (1.f / (float)NN) - mu * mu;
        float inv = rsqrtf(var + GCU_EPS) * gf[t];
        sc[t] = inv;
        sh[t] = bef[t] - mu * inv;
    }
    __syncthreads();
    int i = blockIdx.x * 256 + t, st = gridDim.x * 256;
    for (; i < NN * COUT; i += st) {
        int c = i & 127;
        out[i] = out[i] * sc[c] + sh[c];
    }
}

// ---------------------------------------------------------------------------
extern "C" void kernel_launch(void* const* d_in, const int* in_sizes, int n_in,
                              void* d_out, int out_size) {
    const float* x     = (const float*)d_in[0];
    const int*   tpl_e = (const int*)d_in[1];
    const int*   geo_e = (const int*)d_in[2];
    const float* prm[2][8];
    for (int c = 0; c < 2; c++)
        for (int k = 0; k < 8; k++)
            prm[c][k] = (const float*)d_in[3 + c * 8 + k];
    const float* mlp_W  = (const float*)d_in[19];
    const float* mlp_b  = (const float*)d_in[20];
    const float* mlp_g  = (const float*)d_in[21];
    const float* mlp_be = (const float*)d_in[22];
    float* out = (float*)d_out;

    static int attr_done = 0;
    if (!attr_done) {
        cudaFuncSetAttribute(k_final_gemm_mma,
                             cudaFuncAttributeMaxDynamicSharedMemorySize, FG_SMEM);
        cudaFuncSetAttribute(k_edge_gemm_mma,
                             cudaFuncAttributeMaxDynamicSharedMemorySize, EG_SMEM);
        attr_done = 1;
    }

    k_clear<<<2048, 256>>>();
    for (int conv = 0; conv < 2; conv++) {
        const int* ei = conv ? geo_e : tpl_e;
        k_hist_init<<<256, 256>>>();
        k_hist_count<<<1024, 256>>>(ei + EE);
        k_scanA<<<NBLK, 256>>>();
        k_scanB<<<1, 32>>>();
        k_scanC<<<NBLK, 256>>>();
        k_scatter<<<1024, 256>>>(ei, ei + EE);
        k_precompute<<<1024, 256>>>(x, prm[conv][0], prm[conv][1]);
        k_edge_stats<<<2048, 256>>>(conv * 4 * HH);
        k_edge_gemm_mma<<<444, 256, EG_SMEM>>>(prm[conv][4], prm[conv][5],
                                               prm[conv][2], prm[conv][3],
                                               conv * 4 * HH, conv * NN * HH);
    }
    k_final_gemm_mma<<<(NN + 127) / 128, 256, FG_SMEM>>>(
        mlp_W, mlp_b, prm[0][6], prm[0][7], prm[1][6], prm[1][7], out);
    k_norm<<<2048, 256>>>(mlp_g, mlp_be, out);
}

// round 16
// speedup vs baseline: 1.1813x; 1.1115x over previous
#include <cuda_runtime.h>
#include <cuda_bf16.h>
#include <cstdint>

// ---------------------------------------------------------------------------
// Dual-EdgeConv (tpl/geo) + final MLP, fp32 math, mma.sync (HMMA) GEMMs.
//   Both convs' edges counting-sorted by dst in ONE pass (doubled buffers).
//   layer1 factorized:  pre1 = P[dst] + B[src]  (both convs precomputed once)
//   Stats pass walks sorted edges contiguously (P-run L1 locality).
//   BN1 fold inlined in the edge GEMM; BN2 fused into the final GEMM.
//   Edge epilogue: transpose + run-merged filtered atomicMax.
// ---------------------------------------------------------------------------

static constexpr int NN   = 100000;
static constexpr int CIN  = 32;
static constexpr int HH   = 64;
static constexpr int COUT = 128;
static constexpr int EE   = 1000000;
static constexpr int MM   = EE + NN;
static constexpr int NTILES = (MM + 127) / 128;
static constexpr int NBLK = (NN + 2047) / 2048;          // 49 scan blocks
#define GCU_EPS 1e-5f

__device__ float    g_P[2 * NN * HH];
__device__ float    g_B[2 * NN * HH];
__device__ unsigned g_nodemax[2 * NN * HH];
__device__ float    g_stats[2 * 4 * HH];
__device__ float    g_fstats[2 * COUT];
__device__ int      g_cnt[2 * NN];
__device__ int      g_bsum[2 * 64];
__device__ int      g_cur[2 * NN];
__device__ int      g_srcS[2 * MM];
__device__ int      g_dstS[2 * MM];

__device__ __forceinline__ uint32_t smem_u32(const void* p) {
    uint32_t a;
    asm("{ .reg .u64 t; cvta.to.shared.u64 t, %1; cvt.u32.u64 %0, t; }" : "=r"(a) : "l"(p));
    return a;
}
__device__ __forceinline__ void ldm_x4(uint32_t* r, uint32_t addr) {
    asm volatile("ldmatrix.sync.aligned.m8n8.x4.shared.b16 {%0,%1,%2,%3}, [%4];"
                 : "=r"(r[0]), "=r"(r[1]), "=r"(r[2]), "=r"(r[3]) : "r"(addr));
}
__device__ __forceinline__ void mma16816(float* c, const uint32_t* a, const uint32_t* b) {
    asm volatile("mma.sync.aligned.m16n8k16.row.col.f32.bf16.bf16.f32 "
                 "{%0,%1,%2,%3}, {%4,%5,%6,%7}, {%8,%9}, {%0,%1,%2,%3};"
                 : "+f"(c[0]), "+f"(c[1]), "+f"(c[2]), "+f"(c[3])
                 : "r"(a[0]), "r"(a[1]), "r"(a[2]), "r"(a[3]), "r"(b[0]), "r"(b[1]));
}
__device__ __forceinline__ void split2(float x, float y, uint32_t& hi, uint32_t& lo) {
    __nv_bfloat162 h2 = __floats2bfloat162_rn(x, y);
    float2 hf = __bfloat1622float2(h2);
    __nv_bfloat162 l2 = __floats2bfloat162_rn(x - hf.x, y - hf.y);
    hi = *(uint32_t*)&h2;
    lo = *(uint32_t*)&l2;
}

// ---------------------------------------------------------------------------
__global__ __launch_bounds__(256) void k_clear() {
    int i  = blockIdx.x * blockDim.x + threadIdx.x;
    int st = gridDim.x * blockDim.x;
    for (int j = i; j < 2 * NN * HH; j += st) g_nodemax[j] = 0x80000000u;  // enc(0.0f)
    for (int n = i; n < 2 * NN; n += st) g_cnt[n] = 1;                     // self loop
    if (i < 2 * 4 * HH) g_stats[i] = 0.f;
    if (i < 2 * COUT) g_fstats[i] = 0.f;
    if (i < 2 * 64) g_bsum[i] = 0;
}

// ---------------- counting sort by dst (both convs in one pass) ------------
__global__ __launch_bounds__(256) void k_hist_count(const int* __restrict__ dT,
                                                    const int* __restrict__ dG) {
    int i  = blockIdx.x * blockDim.x + threadIdx.x;
    int st = gridDim.x * blockDim.x;
    for (int e = i; e < 2 * EE; e += st) {
        int conv = (e >= EE);
        int ee = conv ? e - EE : e;
        int d = conv ? __ldg(&dG[ee]) : __ldg(&dT[ee]);
        atomicAdd(&g_cnt[conv * NN + d], 1);
    }
}
__global__ __launch_bounds__(256) void k_scanA() {
    int b = blockIdx.x, conv = blockIdx.y, t = threadIdx.x, lane = t & 31;
    int base = b * 2048 + t * 8;
    int s = 0;
#pragma unroll
    for (int j = 0; j < 8; j++) {
        int i = base + j;
        if (i < NN) s += g_cnt[conv * NN + i];
    }
#pragma unroll
    for (int d = 16; d > 0; d >>= 1) s += __shfl_down_sync(0xffffffffu, s, d);
    if (lane == 0) atomicAdd(&g_bsum[conv * 64 + b], s);
}
__global__ void k_scanB() {
    int conv = threadIdx.x;   // 2 threads
    if (conv < 2) {
        int run = 0;
        for (int i = 0; i < NBLK; i++) {
            int v = g_bsum[conv * 64 + i];
            g_bsum[conv * 64 + i] = run;
            run += v;
        }
    }
}
__global__ __launch_bounds__(256) void k_scanC() {
    __shared__ int tsum[256];
    int b = blockIdx.x, conv = blockIdx.y, t = threadIdx.x;
    int base = b * 2048 + t * 8;
    int c[8];
    int s = 0;
#pragma unroll
    for (int j = 0; j < 8; j++) {
        int i = base + j;
        c[j] = (i < NN) ? g_cnt[conv * NN + i] : 0;
        s += c[j];
    }
    tsum[t] = s;
    __syncthreads();
    if (t == 0) {
        int run = 0;
        for (int j = 0; j < 256; j++) {
            int v = tsum[j];
            tsum[j] = run;
            run += v;
        }
    }
    __syncthreads();
    int pos = g_bsum[conv * 64 + b] + tsum[t];
#pragma unroll
    for (int j = 0; j < 8; j++) {
        int i = base + j;
        if (i < NN) {
            g_cur[conv * NN + i]  = pos + 1;     // slot pos = self loop
            g_srcS[conv * MM + pos] = i;
            g_dstS[conv * MM + pos] = i;
            pos += c[j];
        }
    }
}
__global__ __launch_bounds__(256) void k_scatter(const int* __restrict__ sT,
                                                 const int* __restrict__ dT,
                                                 const int* __restrict__ sG,
                                                 const int* __restrict__ dG) {
    int i  = blockIdx.x * blockDim.x + threadIdx.x;
    int st = gridDim.x * blockDim.x;
    for (int e = i; e < 2 * EE; e += st) {
        int conv = (e >= EE);
        int ee = conv ? e - EE : e;
        int s = conv ? __ldg(&sG[ee]) : __ldg(&sT[ee]);
        int d = conv ? __ldg(&dG[ee]) : __ldg(&dT[ee]);
        int pos = atomicAdd(&g_cur[conv * NN + d], 1);
        g_srcS[conv * MM + pos] = s;
        g_dstS[conv * MM + pos] = d;
    }
}

// ---------------------------------------------------------------------------
// Node precompute for BOTH convs (conv = blockIdx parity).
__global__ __launch_bounds__(256) void k_precompute2(const float* __restrict__ x,
                                                     const float* __restrict__ W1t,
                                                     const float* __restrict__ b1t,
                                                     const float* __restrict__ W1g,
                                                     const float* __restrict__ b1g) {
    __shared__ float Wp[CIN * HH];
    __shared__ float Wb[CIN * HH];
    __shared__ float b1s[HH];
    int conv = blockIdx.x & 1;
    const float* W1 = conv ? W1g : W1t;
    const float* b1 = conv ? b1g : b1t;
    int poff = conv * NN * HH;
    int t = threadIdx.x, lane = t & 31;
    for (int idx = t; idx < CIN * HH; idx += 256) {
        int c = idx >> 5, k = idx & 31;
        float wa = W1[c * 64 + k];
        float wb = W1[c * 64 + 32 + k];
        Wp[k * HH + c] = wa - wb;
        Wb[k * HH + c] = wb;
    }
    if (t < HH) b1s[t] = b1[t];
    __syncthreads();

    int gw = ((blockIdx.x >> 1) * 256 + t) >> 5;
    int nw = ((gridDim.x >> 1) * 256) >> 5;
    for (int n = gw; n < NN; n += nw) {
        float xv = x[n * CIN + lane];
        float ap  = b1s[lane], ap2 = b1s[lane + 32];
        float ab  = 0.f,       ab2 = 0.f;
#pragma unroll
        for (int k = 0; k < CIN; k++) {
            float xk = __shfl_sync(0xffffffffu, xv, k);
            ap  += xk * Wp[k * HH + lane];
            ap2 += xk * Wp[k * HH + 32 + lane];
            ab  += xk * Wb[k * HH + lane];
            ab2 += xk * Wb[k * HH + 32 + lane];
        }
        g_P[poff + n * HH + lane]      = ap;
        g_P[poff + n * HH + 32 + lane] = ap2;
        g_B[poff + n * HH + lane]      = ab;
        g_B[poff + n * HH + 32 + lane] = ab2;
    }
}

// ---------------------------------------------------------------------------
// BN1 stats over sorted edges, CONTIGUOUS per warp (P-run L1 locality).
// MM % 32 == 0, so the inner loop is a fixed 32 iterations.
__global__ __launch_bounds__(256) void k_edge_stats(int eoff, int poff, int coff) {
    __shared__ float red[2 * HH];
    int t = threadIdx.x, lane = t & 31;
    int gw = (blockIdx.x * 256 + t) >> 5;
    int nw = (gridDim.x * 256) >> 5;
    float s0 = 0.f, q0 = 0.f, s1 = 0.f, q1 = 0.f;   // ch 2*lane, 2*lane+1
    for (int base = gw * 32; base < MM; base += nw * 32) {
        int sI = __ldg(&g_srcS[eoff + base + lane]);
        int dI = __ldg(&g_dstS[eoff + base + lane]);
#pragma unroll 4
        for (int e = 0; e < 32; e++) {
            int sE = __shfl_sync(0xffffffffu, sI, e);
            int dE = __shfl_sync(0xffffffffu, dI, e);
            float2 p = *(const float2*)(g_P + poff + (size_t)dE * HH + 2 * lane);
            float2 b = *(const float2*)(g_B + poff + (size_t)sE * HH + 2 * lane);
            float h0 = fmaxf(p.x + b.x, 0.f);
            float h1 = fmaxf(p.y + b.y, 0.f);
            s0 += h0; q0 += h0 * h0;
            s1 += h1; q1 += h1 * h1;
        }
    }
    if (t < 2 * HH) red[t] = 0.f;
    __syncthreads();
    atomicAdd(&red[2 * lane], s0);
    atomicAdd(&red[2 * lane + 1], s1);
    atomicAdd(&red[HH + 2 * lane], q0);
    atomicAdd(&red[HH + 2 * lane + 1], q1);
    __syncthreads();
    if (t < HH) {
        atomicAdd(&g_stats[coff + t], red[t]);
        atomicAdd(&g_stats[coff + HH + t], red[HH + t]);
    }
}

// ---------------------------------------------------------------------------
// Edge GEMM on sorted edges: gather, MMA, transpose + run-merged epilogue.
static constexpr int EG_SMEM = 32768 + 8192 + 8192;

__global__ __launch_bounds__(256, 3) void k_edge_gemm_mma(const float* __restrict__ W2,
                                                          const float* __restrict__ b2,
                                                          const float* __restrict__ g1,
                                                          const float* __restrict__ be1,
                                                          int eoff, int poff,
                                                          int coff, int nmoff) {
    extern __shared__ __align__(16) unsigned char eg_sm[];
    unsigned char* sAbuf = eg_sm;
    uint32_t* sWhi = (uint32_t*)(eg_sm + 32768);
    uint32_t* sWlo = (uint32_t*)(eg_sm + 32768 + 8192);
    __shared__ float aS[HH], dS[HH], b2s[HH];
    __shared__ int dsts[128];
    __shared__ float red[2 * HH];

    unsigned char* sAhi = sAbuf;
    unsigned char* sAlo = sAbuf + 16384;
    float* h2s = (float*)sAbuf;

    int t = threadIdx.x, lane = t & 31, w = t >> 5;
    int wrow = w & 3, wcol = w >> 2;
    int g  = lane >> 2;
    int tg = lane & 3;

    if (t < HH) {
        float mu  = g_stats[coff + t] * (1.f / (float)MM);
        float var = g_stats[coff + HH + t] * (1.f / (float)MM) - mu * mu;
        float av  = g1[t] * rsqrtf(var + GCU_EPS);
        aS[t] = av;
        dS[t] = be1[t] - mu * av;
    }
    __syncthreads();

    if (wrow == 0) {
#pragma unroll
        for (int nb = 0; nb < 4; nb++) {
#pragma unroll
            for (int kb = 0; kb < 4; kb++) {
                int o  = wcol * 32 + nb * 8 + g;
                int k0 = kb * 16 + tg * 2;
                float w00 = W2[o * 64 + k0]     * aS[k0];
                float w01 = W2[o * 64 + k0 + 1] * aS[k0 + 1];
                float w10 = W2[o * 64 + k0 + 8] * aS[k0 + 8];
                float w11 = W2[o * 64 + k0 + 9] * aS[k0 + 9];
                uint32_t h0, l0, h1, l1;
                split2(w00, w01, h0, l0);
                split2(w10, w11, h1, l1);
                int bidx = (((wcol * 4 + nb) * 4 + kb) * 32 + lane) * 2;
                sWhi[bidx]     = h0;  sWhi[bidx + 1] = h1;
                sWlo[bidx]     = l0;  sWlo[bidx + 1] = l1;
            }
        }
    }
    if (t < HH) {
        float bb = b2[t];
        for (int c = 0; c < HH; c++) bb += W2[t * 64 + c] * dS[c];
        b2s[t] = bb;
    }
    if (t < 2 * HH) red[t] = 0.f;

    uint32_t aHiBase = smem_u32(sAhi), aLoBase = smem_u32(sAlo);
    int sub = lane >> 3, rr = lane & 7;
    uint32_t addrA[2][4];
#pragma unroll
    for (int mb = 0; mb < 2; mb++)
#pragma unroll
        for (int kb = 0; kb < 4; kb++) {
            int r    = wrow * 32 + mb * 16 + (sub & 1) * 8 + rr;
            int colb = kb * 32 + (sub >> 1) * 16;
            addrA[mb][kb] = (uint32_t)(r * 128 + (colb ^ ((r & 7) << 4)));
        }

    float s0 = 0.f, q0 = 0.f, s1 = 0.f, q1 = 0.f;
    __syncthreads();
    float b2a = b2s[lane];
    float b2b = b2s[lane + 32];

    unsigned* nmBase = g_nodemax + nmoff;
    for (int tile = blockIdx.x; tile < NTILES; tile += gridDim.x) {
        __syncthreads();

        // ---- gather (sorted: dst run-coherent) ----
        int sI = 0, dI = -1;
        if (lane < 16) {
            int mye = tile * 128 + w * 16 + lane;
            if (mye < MM) { sI = __ldg(&g_srcS[eoff + mye]); dI = __ldg(&g_dstS[eoff + mye]); }
            dsts[w * 16 + lane] = dI;
        }
#pragma unroll 8
        for (int e = 0; e < 16; e++) {
            int sE = __shfl_sync(0xffffffffu, sI, e);
            int dE = __shfl_sync(0xffffffffu, dI, e);
            int r  = w * 16 + e;
            float h0 = 0.f, h1 = 0.f;
            if (dE >= 0) {
                float2 p = *(const float2*)(g_P + poff + (size_t)dE * HH + 2 * lane);
                float2 b = *(const float2*)(g_B + poff + (size_t)sE * HH + 2 * lane);
                h0 = fmaxf(p.x + b.x, 0.f);
                h1 = fmaxf(p.y + b.y, 0.f);
            }
            uint32_t hiw, low;
            split2(h0, h1, hiw, low);
            int off = r * 128 + ((lane * 4) ^ ((r & 7) << 4));
            *(uint32_t*)(sAhi + off) = hiw;
            *(uint32_t*)(sAlo + off) = low;
        }
        __syncthreads();

        // ---- MMA ----
        float acc[2][4][4];
#pragma unroll
        for (int mb = 0; mb < 2; mb++)
#pragma unroll
            for (int nb = 0; nb < 4; nb++)
#pragma unroll
                for (int j = 0; j < 4; j++) acc[mb][nb][j] = 0.f;

#pragma unroll
        for (int kb = 0; kb < 4; kb++) {
            uint32_t ahi[2][4], alo[2][4];
#pragma unroll
            for (int mb = 0; mb < 2; mb++) {
                ldm_x4(ahi[mb], aHiBase + addrA[mb][kb]);
                ldm_x4(alo[mb], aLoBase + addrA[mb][kb]);
            }
#pragma unroll
            for (int nb = 0; nb < 4; nb++) {
                int bidx = (((wcol * 4 + nb) * 4 + kb) * 32 + lane) * 2;
                uint2 wh = *(const uint2*)&sWhi[bidx];
                uint2 wl = *(const uint2*)&sWlo[bidx];
                uint32_t whi2[2] = { wh.x, wh.y };
                uint32_t wlo2[2] = { wl.x, wl.y };
#pragma unroll
                for (int mb = 0; mb < 2; mb++) {
                    mma16816(acc[mb][nb], ahi[mb], whi2);
                    mma16816(acc[mb][nb], alo[mb], whi2);
                    mma16816(acc[mb][nb], ahi[mb], wlo2);
                }
            }
        }
        __syncthreads();

        // ---- transpose store ----
#pragma unroll
        for (int mb = 0; mb < 2; mb++) {
#pragma unroll
            for (int half = 0; half < 2; half++) {
                int r  = wrow * 32 + mb * 16 + half * 8 + g;
                int sw = (r & 7) << 3;
#pragma unroll
                for (int nb = 0; nb < 4; nb++) {
                    int ch = wcol * 32 + nb * 8 + tg * 2;
                    float2 v = make_float2(acc[mb][nb][half * 2], acc[mb][nb][half * 2 + 1]);
                    *(float2*)&h2s[r * 64 + (ch ^ sw)] = v;
                }
            }
        }
        __syncthreads();

        // ---- run-merged filtered atomicMax + stats ----
        {
            int prevd = -1;
            float m0 = 0.f, m1 = 0.f;
            for (int i = 0; i < 16; i++) {
                int r = w * 16 + i;
                int d = dsts[r];
                if (d < 0) continue;
                int sw = (r & 7) << 3;
                float v0 = fmaxf(h2s[r * 64 + (lane ^ sw)] + b2a, 0.f);
                float v1 = fmaxf(h2s[r * 64 + ((lane + 32) ^ sw)] + b2b, 0.f);
                s0 += v0; q0 += v0 * v0;
                s1 += v1; q1 += v1 * v1;
                if (d != prevd) {
                    if (prevd >= 0) {
                        unsigned* nm = nmBase + (size_t)prevd * HH;
                        unsigned c0 = __ldg(&nm[lane]);
                        unsigned c1 = __ldg(&nm[lane + 32]);
                        unsigned e0v = __float_as_uint(m0) | 0x80000000u;
                        unsigned e1v = __float_as_uint(m1) | 0x80000000u;
                        if (e0v > c0) atomicMax(&nm[lane], e0v);
                        if (e1v > c1) atomicMax(&nm[lane + 32], e1v);
                    }
                    prevd = d;
                    m0 = v0;
                    m1 = v1;
                } else {
                    m0 = fmaxf(m0, v0);
                    m1 = fmaxf(m1, v1);
                }
            }
            if (prevd >= 0) {
                unsigned* nm = nmBase + (size_t)prevd * HH;
                unsigned c0 = __ldg(&nm[lane]);
                unsigned c1 = __ldg(&nm[lane + 32]);
                unsigned e0v = __float_as_uint(m0) | 0x80000000u;
                unsigned e1v = __float_as_uint(m1) | 0x80000000u;
                if (e0v > c0) atomicMax(&nm[lane], e0v);
                if (e1v > c1) atomicMax(&nm[lane + 32], e1v);
            }
        }
    }

    __syncthreads();
    atomicAdd(&red[lane], s0);
    atomicAdd(&red[lane + 32], s1);
    atomicAdd(&red[HH + lane], q0);
    atomicAdd(&red[HH + lane + 32], q1);
    __syncthreads();
    if (t < HH) {
        atomicAdd(&g_stats[coff + 2 * HH + t], red[t]);
        atomicAdd(&g_stats[coff + 3 * HH + t], red[HH + t]);
    }
}

// ---------------------------------------------------------------------------
// Final MLP GEMM: reads nodemax directly, applies BN2 affine inline.
static constexpr int FG_SMEM = 4 * 32768;

__global__ __launch_bounds__(256) void k_final_gemm_mma(const float* __restrict__ Wf,
                                                        const float* __restrict__ bf,
                                                        const float* __restrict__ g2a,
                                                        const float* __restrict__ be2a,
                                                        const float* __restrict__ g2b,
                                                        const float* __restrict__ be2b,
                                                        float* __restrict__ out) {
    extern __shared__ __align__(16) unsigned char sm[];
    unsigned char* sXhi = sm;
    unsigned char* sXlo = sm + 32768;
    uint32_t* sWhi = (uint32_t*)(sm + 65536);
    uint32_t* sWloF = (uint32_t*)(sm + 65536 + 32768);
    __shared__ float bsh[COUT];
    __shared__ float red[2 * COUT];
    __shared__ float sc2[COUT], sh2[COUT];

    int t = threadIdx.x, lane = t & 31, w = t >> 5;
    int wrow = w & 3, wcol = w >> 2;
    int g = lane >> 2, tg = lane & 3;

    if (t < COUT) {
        bsh[t] = bf[t];
        int conv = t >> 6, c = t & 63;
        float mu  = g_stats[conv * 4 * HH + 2 * HH + c] * (1.f / (float)MM);
        float var = g_stats[conv * 4 * HH + 3 * HH + c] * (1.f / (float)MM) - mu * mu;
        float gv  = conv ? g2b[c] : g2a[c];
        float bev = conv ? be2b[c] : be2a[c];
        float inv = rsqrtf(var + GCU_EPS) * gv;
        sc2[t] = inv;
        sh2[t] = bev - mu * inv;
    }
    red[t] = 0.f;

    for (int i = 0; i < 16; i++) {
        int set  = w * 16 + i;
        int swc  = set >> 6, snb = (set >> 3) & 7, skb = set & 7;
        int o    = swc * 64 + snb * 8 + g;
        int k0   = skb * 16 + tg * 2;
        const float* Wr = Wf + o * COUT + k0;
        uint32_t h0, l0, h1, l1;
        split2(Wr[0], Wr[1], h0, l0);
        split2(Wr[8], Wr[9], h1, l1);
        int bidx = (((swc * 8 + snb) * 8 + skb) * 32 + lane) * 2;
        sWhi[bidx]      = h0;  sWhi[bidx + 1]  = h1;
        sWloF[bidx]     = l0;  sWloF[bidx + 1] = l1;
    }
    __syncthreads();

    int nbase = blockIdx.x * 128;
    for (int idx = t; idx < 128 * 64; idx += 256) {
        int r = idx >> 6, pp = idx & 63;
        int chunk = pp >> 5, p = pp & 31;
        int n = nbase + r;
        float vx = 0.f, vy = 0.f;
        if (n < NN) {
            uint2 mv = *(const uint2*)&g_nodemax[(size_t)chunk * NN * HH + n * HH + 2 * p];
            int ch = chunk * 64 + 2 * p;
            vx = __uint_as_float(mv.x & 0x7fffffffu) * sc2[ch]     + sh2[ch];
            vy = __uint_as_float(mv.y & 0x7fffffffu) * sc2[ch + 1] + sh2[ch + 1];
        }
        uint32_t hiw, low;
        split2(vx, vy, hiw, low);
        int off = chunk * 16384 + r * 128 + ((p * 4) ^ ((r & 7) << 4));
        *(uint32_t*)(sXhi + off) = hiw;
        *(uint32_t*)(sXlo + off) = low;
    }
    __syncthreads();

    float acc[2][8][4];
#pragma unroll
    for (int mb = 0; mb < 2; mb++)
#pragma unroll
        for (int nb = 0; nb < 8; nb++)
#pragma unroll
            for (int j = 0; j < 4; j++) acc[mb][nb][j] = 0.f;

    uint32_t xHiBase = smem_u32(sXhi), xLoBase = smem_u32(sXlo);
    int sub = lane >> 3, rr = lane & 7;
#pragma unroll
    for (int kb = 0; kb < 8; kb++) {
        int chunk = kb >> 2, kk = kb & 3;
        uint32_t ahi[2][4], alo[2][4];
#pragma unroll
        for (int mb = 0; mb < 2; mb++) {
            int r    = wrow * 32 + mb * 16 + (sub & 1) * 8 + rr;
            int colb = kk * 32 + (sub >> 1) * 16;
            uint32_t a = (uint32_t)(chunk * 16384 + r * 128 + (colb ^ ((r & 7) << 4)));
            ldm_x4(ahi[mb], xHiBase + a);
            ldm_x4(alo[mb], xLoBase + a);
        }
#pragma unroll
        for (int nb = 0; nb < 8; nb++) {
            int bidx = (((wcol * 8 + nb) * 8 + kb) * 32 + lane) * 2;
            uint2 wh = *(const uint2*)&sWhi[bidx];
            uint2 wl = *(const uint2*)&sWloF[bidx];
            uint32_t whi2[2] = { wh.x, wh.y };
            uint32_t wlo2[2] = { wl.x, wl.y };
#pragma unroll
            for (int mb = 0; mb < 2; mb++) {
                mma16816(acc[mb][nb], ahi[mb], whi2);
                mma16816(acc[mb][nb], alo[mb], whi2);
                mma16816(acc[mb][nb], ahi[mb], wlo2);
            }
        }
    }

    float ls[16], lq[16];
#pragma unroll
    for (int i = 0; i < 16; i++) { ls[i] = 0.f; lq[i] = 0.f; }
#pragma unroll
    for (int mb = 0; mb < 2; mb++) {
#pragma unroll
        for (int half = 0; half < 2; half++) {
            int n = nbase + wrow * 32 + mb * 16 + half * 8 + g;
            if (n >= NN) continue;
#pragma unroll
            for (int nb = 0; nb < 8; nb++) {
                int o = wcol * 64 + nb * 8 + tg * 2;
                float v0 = fmaxf(acc[mb][nb][half * 2]     + bsh[o],     0.f);
                float v1 = fmaxf(acc[mb][nb][half * 2 + 1] + bsh[o + 1], 0.f);
                out[n * COUT + o]     = v0;
                out[n * COUT + o + 1] = v1;
                ls[nb * 2]     += v0; lq[nb * 2]     += v0 * v0;
                ls[nb * 2 + 1] += v1; lq[nb * 2 + 1] += v1 * v1;
            }
        }
    }
#pragma unroll
    for (int i = 0; i < 16; i++) {
#pragma unroll
        for (int dlt = 16; dlt >= 4; dlt >>= 1) {
            ls[i] += __shfl_down_sync(0xffffffffu, ls[i], dlt);
            lq[i] += __shfl_down_sync(0xffffffffu, lq[i], dlt);
        }
    }
    if (lane < 4) {
#pragma unroll
        for (int nb = 0; nb < 8; nb++) {
            int o = wcol * 64 + nb * 8 + tg * 2;
            atomicAdd(&red[o],            ls[nb * 2]);
            atomicAdd(&red[o + 1],        ls[nb * 2 + 1]);
            atomicAdd(&red[COUT + o],     lq[nb * 2]);
            atomicAdd(&red[COUT + o + 1], lq[nb * 2 + 1]);
        }
    }
    __syncthreads();
    if (t < COUT) {
        atomicAdd(&g_fstats[t],        red[t]);
        atomicAdd(&g_fstats[COUT + t], red[COUT + t]);
    }
}

// ---------------------------------------------------------------------------
__global__ __launch_bounds__(256) void k_norm(const float* __restrict__ gf,
                                              const float* __restrict__ bef,
                                              float* __restrict__ out) {
    __shared__ float sc[COUT], sh[COUT];
    int t = threadIdx.x;
    if (t < COUT) {
        float mu  = g_fstats[t] * (1.f / (float)NN);
        float var = g_fstats[COUT + t] * (1.f / (float)NN) - mu * mu;
        float inv = rsqrtf(var + GCU_EPS) * gf[t];
        sc[t] = inv;
        sh[t] = bef[t] - mu * inv;
    }
    __syncthreads();
    int i = blockIdx.x * 256 + t, st = gridDim.x * 256;
    for (; i < NN * COUT; i += st) {
        int c = i & 127;
        out[i] = out[i] * sc[c] + sh[c];
    }
}

// ---------------------------------------------------------------------------
extern "C" void kernel_launch(void* const* d_in, const int* in_sizes, int n_in,
                              void* d_out, int out_size) {
    const float* x     = (const float*)d_in[0];
    const int*   tpl_e = (const int*)d_in[1];
    const int*   geo_e = (const int*)d_in[2];
    const float* prm[2][8];
    for (int c = 0; c < 2; c++)
        for (int k = 0; k < 8; k++)
            prm[c][k] = (const float*)d_in[3 + c * 8 + k];
    const float* mlp_W  = (const float*)d_in[19];
    const float* mlp_b  = (const float*)d_in[20];
    const float* mlp_g  = (const float*)d_in[21];
    const float* mlp_be = (const float*)d_in[22];
    float* out = (float*)d_out;

    static int attr_done = 0;
    if (!attr_done) {
        cudaFuncSetAttribute(k_final_gemm_mma,
                             cudaFuncAttributeMaxDynamicSharedMemorySize, FG_SMEM);
        cudaFuncSetAttribute(k_edge_gemm_mma,
                             cudaFuncAttributeMaxDynamicSharedMemorySize, EG_SMEM);
        attr_done = 1;
    }

    k_clear<<<2048, 256>>>();
    k_hist_count<<<2048, 256>>>(tpl_e + EE, geo_e + EE);
    k_scanA<<<dim3(NBLK, 2), 256>>>();
    k_scanB<<<1, 2>>>();
    k_scanC<<<dim3(NBLK, 2), 256>>>();
    k_scatter<<<2048, 256>>>(tpl_e, tpl_e + EE, geo_e, geo_e + EE);
    k_precompute2<<<2048, 256>>>(x, prm[0][0], prm[0][1], prm[1][0], prm[1][1]);
    for (int conv = 0; conv < 2; conv++) {
        k_edge_stats<<<2048, 256>>>(conv * MM, conv * NN * HH, conv * 4 * HH);
        k_edge_gemm_mma<<<444, 256, EG_SMEM>>>(prm[conv][4], prm[conv][5],
                                               prm[conv][2], prm[conv][3],
                                               conv * MM, conv * NN * HH,
                                               conv * 4 * HH, conv * NN * HH);
    }
    k_final_gemm_mma<<<(NN + 127) / 128, 256, FG_SMEM>>>(
        mlp_W, mlp_b, prm[0][6], prm[0][7], prm[1][6], prm[1][7], out);
    k_norm<<<2048, 256>>>(mlp_g, mlp_be, out);
}

// round 17
// speedup vs baseline: 1.2019x; 1.0174x over previous
#include <cuda_runtime.h>
#include <cuda_bf16.h>
#include <cstdint>

// ---------------------------------------------------------------------------
// Dual-EdgeConv (tpl/geo) + final MLP, fp32 math, mma.sync (HMMA) GEMMs.
//   Both convs' edges grouped by dst in ONE pass (hist + warp-aggregated
//   region allocator + scatter; run placement arbitrary, runs contiguous).
//   layer1 factorized:  pre1 = P[dst] + B[src]  (both convs precomputed once)
//   Stats + edge GEMM launched once for BOTH convs (blockIdx.y = conv).
//   BN1 fold inlined in the edge GEMM; BN2 fused into the final GEMM.
//   Edge epilogue: transpose + run-merged filtered atomicMax.
// ---------------------------------------------------------------------------

static constexpr int NN   = 100000;
static constexpr int CIN  = 32;
static constexpr int HH   = 64;
static constexpr int COUT = 128;
static constexpr int EE   = 1000000;
static constexpr int MM   = EE + NN;
static constexpr int NTILES = (MM + 127) / 128;
#define GCU_EPS 1e-5f

__device__ float    g_P[2 * NN * HH];
__device__ float    g_B[2 * NN * HH];
__device__ unsigned g_nodemax[2 * NN * HH];
__device__ float    g_stats[2 * 4 * HH];
__device__ float    g_fstats[2 * COUT];
__device__ int      g_cnt[2 * NN];
__device__ int      g_total[2];
__device__ int      g_cur[2 * NN];
__device__ int      g_srcS[2 * MM];
__device__ int      g_dstS[2 * MM];

__device__ __forceinline__ uint32_t smem_u32(const void* p) {
    uint32_t a;
    asm("{ .reg .u64 t; cvta.to.shared.u64 t, %1; cvt.u32.u64 %0, t; }" : "=r"(a) : "l"(p));
    return a;
}
__device__ __forceinline__ void ldm_x4(uint32_t* r, uint32_t addr) {
    asm volatile("ldmatrix.sync.aligned.m8n8.x4.shared.b16 {%0,%1,%2,%3}, [%4];"
                 : "=r"(r[0]), "=r"(r[1]), "=r"(r[2]), "=r"(r[3]) : "r"(addr));
}
__device__ __forceinline__ void mma16816(float* c, const uint32_t* a, const uint32_t* b) {
    asm volatile("mma.sync.aligned.m16n8k16.row.col.f32.bf16.bf16.f32 "
                 "{%0,%1,%2,%3}, {%4,%5,%6,%7}, {%8,%9}, {%0,%1,%2,%3};"
                 : "+f"(c[0]), "+f"(c[1]), "+f"(c[2]), "+f"(c[3])
                 : "r"(a[0]), "r"(a[1]), "r"(a[2]), "r"(a[3]), "r"(b[0]), "r"(b[1]));
}
__device__ __forceinline__ void split2(float x, float y, uint32_t& hi, uint32_t& lo) {
    __nv_bfloat162 h2 = __floats2bfloat162_rn(x, y);
    float2 hf = __bfloat1622float2(h2);
    __nv_bfloat162 l2 = __floats2bfloat162_rn(x - hf.x, y - hf.y);
    hi = *(uint32_t*)&h2;
    lo = *(uint32_t*)&l2;
}

// ---------------------------------------------------------------------------
__global__ __launch_bounds__(256) void k_clear() {
    int i  = blockIdx.x * blockDim.x + threadIdx.x;
    int st = gridDim.x * blockDim.x;
    for (int j = i; j < 2 * NN * HH; j += st) g_nodemax[j] = 0x80000000u;  // enc(0.0f)
    for (int n = i; n < 2 * NN; n += st) g_cnt[n] = 1;                     // self loop
    if (i < 2 * 4 * HH) g_stats[i] = 0.f;
    if (i < 2 * COUT) g_fstats[i] = 0.f;
    if (i < 2) g_total[i] = 0;
}

// ---------------- dst grouping (both convs in one pass) --------------------
__global__ __launch_bounds__(256) void k_hist_count(const int* __restrict__ dT,
                                                    const int* __restrict__ dG) {
    int i  = blockIdx.x * blockDim.x + threadIdx.x;
    int st = gridDim.x * blockDim.x;
    for (int e = i; e < 2 * EE; e += st) {
        int conv = (e >= EE);
        int ee = conv ? e - EE : e;
        int d = conv ? __ldg(&dG[ee]) : __ldg(&dT[ee]);
        atomicAdd(&g_cnt[conv * NN + d], 1);
    }
}
// Warp-aggregated region allocator: per-node contiguous region, arbitrary order.
__global__ __launch_bounds__(256) void k_alloc() {
    int conv = blockIdx.y;
    int n = blockIdx.x * 256 + threadIdx.x;
    int lane = threadIdx.x & 31;
    bool valid = (n < NN);
    int c = valid ? g_cnt[conv * NN + n] : 0;
    int p = c;
#pragma unroll
    for (int d = 1; d < 32; d <<= 1) {
        int v = __shfl_up_sync(0xffffffffu, p, d);
        if (lane >= d) p += v;
    }
    int total = __shfl_sync(0xffffffffu, p, 31);
    int base = 0;
    if (lane == 31) base = atomicAdd(&g_total[conv], total);
    base = __shfl_sync(0xffffffffu, base, 31);
    int pos = base + p - c;          // exclusive prefix
    if (valid) {
        g_cur[conv * NN + n]    = pos + 1;   // slot pos = self loop
        g_srcS[conv * MM + pos] = n;
        g_dstS[conv * MM + pos] = n;
    }
}
__global__ __launch_bounds__(256) void k_scatter(const int* __restrict__ sT,
                                                 const int* __restrict__ dT,
                                                 const int* __restrict__ sG,
                                                 const int* __restrict__ dG) {
    int i  = blockIdx.x * blockDim.x + threadIdx.x;
    int st = gridDim.x * blockDim.x;
    for (int e = i; e < 2 * EE; e += st) {
        int conv = (e >= EE);
        int ee = conv ? e - EE : e;
        int s = conv ? __ldg(&sG[ee]) : __ldg(&sT[ee]);
        int d = conv ? __ldg(&dG[ee]) : __ldg(&dT[ee]);
        int pos = atomicAdd(&g_cur[conv * NN + d], 1);
        g_srcS[conv * MM + pos] = s;
        g_dstS[conv * MM + pos] = d;
    }
}

// ---------------------------------------------------------------------------
// Node precompute for BOTH convs (conv = blockIdx parity).
__global__ __launch_bounds__(256) void k_precompute2(const float* __restrict__ x,
                                                     const float* __restrict__ W1t,
                                                     const float* __restrict__ b1t,
                                                     const float* __restrict__ W1g,
                                                     const float* __restrict__ b1g) {
    __shared__ float Wp[CIN * HH];
    __shared__ float Wb[CIN * HH];
    __shared__ float b1s[HH];
    int conv = blockIdx.x & 1;
    const float* W1 = conv ? W1g : W1t;
    const float* b1 = conv ? b1g : b1t;
    int poff = conv * NN * HH;
    int t = threadIdx.x, lane = t & 31;
    for (int idx = t; idx < CIN * HH; idx += 256) {
        int c = idx >> 5, k = idx & 31;
        float wa = W1[c * 64 + k];
        float wb = W1[c * 64 + 32 + k];
        Wp[k * HH + c] = wa - wb;
        Wb[k * HH + c] = wb;
    }
    if (t < HH) b1s[t] = b1[t];
    __syncthreads();

    int gw = ((blockIdx.x >> 1) * 256 + t) >> 5;
    int nw = ((gridDim.x >> 1) * 256) >> 5;
    for (int n = gw; n < NN; n += nw) {
        float xv = x[n * CIN + lane];
        float ap  = b1s[lane], ap2 = b1s[lane + 32];
        float ab  = 0.f,       ab2 = 0.f;
#pragma unroll
        for (int k = 0; k < CIN; k++) {
            float xk = __shfl_sync(0xffffffffu, xv, k);
            ap  += xk * Wp[k * HH + lane];
            ap2 += xk * Wp[k * HH + 32 + lane];
            ab  += xk * Wb[k * HH + lane];
            ab2 += xk * Wb[k * HH + 32 + lane];
        }
        g_P[poff + n * HH + lane]      = ap;
        g_P[poff + n * HH + 32 + lane] = ap2;
        g_B[poff + n * HH + lane]      = ab;
        g_B[poff + n * HH + 32 + lane] = ab2;
    }
}

// ---------------------------------------------------------------------------
// BN1 stats over grouped edges, contiguous per warp, BOTH convs (blockIdx.y).
__global__ __launch_bounds__(256) void k_edge_stats() {
    __shared__ float red[2 * HH];
    int conv = blockIdx.y;
    int eoff = conv * MM, poff = conv * NN * HH, coff = conv * 4 * HH;
    int t = threadIdx.x, lane = t & 31;
    int gw = (blockIdx.x * 256 + t) >> 5;
    int nw = (gridDim.x * 256) >> 5;
    float s0 = 0.f, q0 = 0.f, s1 = 0.f, q1 = 0.f;   // ch 2*lane, 2*lane+1
    for (int base = gw * 32; base < MM; base += nw * 32) {
        int sI = __ldg(&g_srcS[eoff + base + lane]);
        int dI = __ldg(&g_dstS[eoff + base + lane]);
#pragma unroll 4
        for (int e = 0; e < 32; e++) {
            int sE = __shfl_sync(0xffffffffu, sI, e);
            int dE = __shfl_sync(0xffffffffu, dI, e);
            float2 p = *(const float2*)(g_P + poff + (size_t)dE * HH + 2 * lane);
            float2 b = *(const float2*)(g_B + poff + (size_t)sE * HH + 2 * lane);
            float h0 = fmaxf(p.x + b.x, 0.f);
            float h1 = fmaxf(p.y + b.y, 0.f);
            s0 += h0; q0 += h0 * h0;
            s1 += h1; q1 += h1 * h1;
        }
    }
    if (t < 2 * HH) red[t] = 0.f;
    __syncthreads();
    atomicAdd(&red[2 * lane], s0);
    atomicAdd(&red[2 * lane + 1], s1);
    atomicAdd(&red[HH + 2 * lane], q0);
    atomicAdd(&red[HH + 2 * lane + 1], q1);
    __syncthreads();
    if (t < HH) {
        atomicAdd(&g_stats[coff + t], red[t]);
        atomicAdd(&g_stats[coff + HH + t], red[HH + t]);
    }
}

// ---------------------------------------------------------------------------
// Edge GEMM for BOTH convs (blockIdx.y): gather, MMA, transpose + run-merge.
static constexpr int EG_SMEM = 32768 + 8192 + 8192;

__global__ __launch_bounds__(256, 3) void k_edge_gemm_mma(
        const float* __restrict__ W2t, const float* __restrict__ b2t,
        const float* __restrict__ g1t, const float* __restrict__ be1t,
        const float* __restrict__ W2g, const float* __restrict__ b2g,
        const float* __restrict__ g1g, const float* __restrict__ be1g) {
    extern __shared__ __align__(16) unsigned char eg_sm[];
    unsigned char* sAbuf = eg_sm;
    uint32_t* sWhi = (uint32_t*)(eg_sm + 32768);
    uint32_t* sWlo = (uint32_t*)(eg_sm + 32768 + 8192);
    __shared__ float aS[HH], dS[HH], b2s[HH];
    __shared__ int dsts[128];
    __shared__ float red[2 * HH];

    unsigned char* sAhi = sAbuf;
    unsigned char* sAlo = sAbuf + 16384;
    float* h2s = (float*)sAbuf;

    int conv = blockIdx.y;
    const float* W2  = conv ? W2g  : W2t;
    const float* b2  = conv ? b2g  : b2t;
    const float* g1  = conv ? g1g  : g1t;
    const float* be1 = conv ? be1g : be1t;
    int eoff = conv * MM, poff = conv * NN * HH;
    int coff = conv * 4 * HH, nmoff = conv * NN * HH;

    int t = threadIdx.x, lane = t & 31, w = t >> 5;
    int wrow = w & 3, wcol = w >> 2;
    int g  = lane >> 2;
    int tg = lane & 3;

    if (t < HH) {
        float mu  = g_stats[coff + t] * (1.f / (float)MM);
        float var = g_stats[coff + HH + t] * (1.f / (float)MM) - mu * mu;
        float av  = g1[t] * rsqrtf(var + GCU_EPS);
        aS[t] = av;
        dS[t] = be1[t] - mu * av;
    }
    __syncthreads();

    if (wrow == 0) {
#pragma unroll
        for (int nb = 0; nb < 4; nb++) {
#pragma unroll
            for (int kb = 0; kb < 4; kb++) {
                int o  = wcol * 32 + nb * 8 + g;
                int k0 = kb * 16 + tg * 2;
                float w00 = W2[o * 64 + k0]     * aS[k0];
                float w01 = W2[o * 64 + k0 + 1] * aS[k0 + 1];
                float w10 = W2[o * 64 + k0 + 8] * aS[k0 + 8];
                float w11 = W2[o * 64 + k0 + 9] * aS[k0 + 9];
                uint32_t h0, l0, h1, l1;
                split2(w00, w01, h0, l0);
                split2(w10, w11, h1, l1);
                int bidx = (((wcol * 4 + nb) * 4 + kb) * 32 + lane) * 2;
                sWhi[bidx]     = h0;  sWhi[bidx + 1] = h1;
                sWlo[bidx]     = l0;  sWlo[bidx + 1] = l1;
            }
        }
    }
    if (t < HH) {
        float bb = b2[t];
        for (int c = 0; c < HH; c++) bb += W2[t * 64 + c] * dS[c];
        b2s[t] = bb;
    }
    if (t < 2 * HH) red[t] = 0.f;

    uint32_t aHiBase = smem_u32(sAhi), aLoBase = smem_u32(sAlo);
    int sub = lane >> 3, rr = lane & 7;
    uint32_t addrA[2][4];
#pragma unroll
    for (int mb = 0; mb < 2; mb++)
#pragma unroll
        for (int kb = 0; kb < 4; kb++) {
            int r    = wrow * 32 + mb * 16 + (sub & 1) * 8 + rr;
            int colb = kb * 32 + (sub >> 1) * 16;
            addrA[mb][kb] = (uint32_t)(r * 128 + (colb ^ ((r & 7) << 4)));
        }

    float s0 = 0.f, q0 = 0.f, s1 = 0.f, q1 = 0.f;
    __syncthreads();
    float b2a = b2s[lane];
    float b2b = b2s[lane + 32];

    unsigned* nmBase = g_nodemax + nmoff;
    for (int tile = blockIdx.x; tile < NTILES; tile += gridDim.x) {
        __syncthreads();

        // ---- gather (grouped: dst run-coherent) ----
        int sI = 0, dI = -1;
        if (lane < 16) {
            int mye = tile * 128 + w * 16 + lane;
            if (mye < MM) { sI = __ldg(&g_srcS[eoff + mye]); dI = __ldg(&g_dstS[eoff + mye]); }
            dsts[w * 16 + lane] = dI;
        }
#pragma unroll 8
        for (int e = 0; e < 16; e++) {
            int sE = __shfl_sync(0xffffffffu, sI, e);
            int dE = __shfl_sync(0xffffffffu, dI, e);
            int r  = w * 16 + e;
            float h0 = 0.f, h1 = 0.f;
            if (dE >= 0) {
                float2 p = *(const float2*)(g_P + poff + (size_t)dE * HH + 2 * lane);
                float2 b = *(const float2*)(g_B + poff + (size_t)sE * HH + 2 * lane);
                h0 = fmaxf(p.x + b.x, 0.f);
                h1 = fmaxf(p.y + b.y, 0.f);
            }
            uint32_t hiw, low;
            split2(h0, h1, hiw, low);
            int off = r * 128 + ((lane * 4) ^ ((r & 7) << 4));
            *(uint32_t*)(sAhi + off) = hiw;
            *(uint32_t*)(sAlo + off) = low;
        }
        __syncthreads();

        // ---- MMA ----
        float acc[2][4][4];
#pragma unroll
        for (int mb = 0; mb < 2; mb++)
#pragma unroll
            for (int nb = 0; nb < 4; nb++)
#pragma unroll
                for (int j = 0; j < 4; j++) acc[mb][nb][j] = 0.f;

#pragma unroll
        for (int kb = 0; kb < 4; kb++) {
            uint32_t ahi[2][4], alo[2][4];
#pragma unroll
            for (int mb = 0; mb < 2; mb++) {
                ldm_x4(ahi[mb], aHiBase + addrA[mb][kb]);
                ldm_x4(alo[mb], aLoBase + addrA[mb][kb]);
            }
#pragma unroll
            for (int nb = 0; nb < 4; nb++) {
                int bidx = (((wcol * 4 + nb) * 4 + kb) * 32 + lane) * 2;
                uint2 wh = *(const uint2*)&sWhi[bidx];
                uint2 wl = *(const uint2*)&sWlo[bidx];
                uint32_t whi2[2] = { wh.x, wh.y };
                uint32_t wlo2[2] = { wl.x, wl.y };
#pragma unroll
                for (int mb = 0; mb < 2; mb++) {
                    mma16816(acc[mb][nb], ahi[mb], whi2);
                    mma16816(acc[mb][nb], alo[mb], whi2);
                    mma16816(acc[mb][nb], ahi[mb], wlo2);
                }
            }
        }
        __syncthreads();

        // ---- transpose store ----
#pragma unroll
        for (int mb = 0; mb < 2; mb++) {
#pragma unroll
            for (int half = 0; half < 2; half++) {
                int r  = wrow * 32 + mb * 16 + half * 8 + g;
                int sw = (r & 7) << 3;
#pragma unroll
                for (int nb = 0; nb < 4; nb++) {
                    int ch = wcol * 32 + nb * 8 + tg * 2;
                    float2 v = make_float2(acc[mb][nb][half * 2], acc[mb][nb][half * 2 + 1]);
                    *(float2*)&h2s[r * 64 + (ch ^ sw)] = v;
                }
            }
        }
        __syncthreads();

        // ---- run-merged filtered atomicMax + stats ----
        {
            int prevd = -1;
            float m0 = 0.f, m1 = 0.f;
            for (int i = 0; i < 16; i++) {
                int r = w * 16 + i;
                int d = dsts[r];
                if (d < 0) continue;
                int sw = (r & 7) << 3;
                float v0 = fmaxf(h2s[r * 64 + (lane ^ sw)] + b2a, 0.f);
                float v1 = fmaxf(h2s[r * 64 + ((lane + 32) ^ sw)] + b2b, 0.f);
                s0 += v0; q0 += v0 * v0;
                s1 += v1; q1 += v1 * v1;
                if (d != prevd) {
                    if (prevd >= 0) {
                        unsigned* nm = nmBase + (size_t)prevd * HH;
                        unsigned c0 = __ldg(&nm[lane]);
                        unsigned c1 = __ldg(&nm[lane + 32]);
                        unsigned e0v = __float_as_uint(m0) | 0x80000000u;
                        unsigned e1v = __float_as_uint(m1) | 0x80000000u;
                        if (e0v > c0) atomicMax(&nm[lane], e0v);
                        if (e1v > c1) atomicMax(&nm[lane + 32], e1v);
                    }
                    prevd = d;
                    m0 = v0;
                    m1 = v1;
                } else {
                    m0 = fmaxf(m0, v0);
                    m1 = fmaxf(m1, v1);
                }
            }
            if (prevd >= 0) {
                unsigned* nm = nmBase + (size_t)prevd * HH;
                unsigned c0 = __ldg(&nm[lane]);
                unsigned c1 = __ldg(&nm[lane + 32]);
                unsigned e0v = __float_as_uint(m0) | 0x80000000u;
                unsigned e1v = __float_as_uint(m1) | 0x80000000u;
                if (e0v > c0) atomicMax(&nm[lane], e0v);
                if (e1v > c1) atomicMax(&nm[lane + 32], e1v);
            }
        }
    }

    __syncthreads();
    atomicAdd(&red[lane], s0);
    atomicAdd(&red[lane + 32], s1);
    atomicAdd(&red[HH + lane], q0);
    atomicAdd(&red[HH + lane + 32], q1);
    __syncthreads();
    if (t < HH) {
        atomicAdd(&g_stats[coff + 2 * HH + t], red[t]);
        atomicAdd(&g_stats[coff + 3 * HH + t], red[HH + t]);
    }
}

// ---------------------------------------------------------------------------
// Final MLP GEMM: reads nodemax directly, applies BN2 affine inline.
static constexpr int FG_SMEM = 4 * 32768;

__global__ __launch_bounds__(256) void k_final_gemm_mma(const float* __restrict__ Wf,
                                                        const float* __restrict__ bf,
                                                        const float* __restrict__ g2a,
                                                        const float* __restrict__ be2a,
                                                        const float* __restrict__ g2b,
                                                        const float* __restrict__ be2b,
                                                        float* __restrict__ out) {
    extern __shared__ __align__(16) unsigned char sm[];
    unsigned char* sXhi = sm;
    unsigned char* sXlo = sm + 32768;
    uint32_t* sWhi = (uint32_t*)(sm + 65536);
    uint32_t* sWloF = (uint32_t*)(sm + 65536 + 32768);
    __shared__ float bsh[COUT];
    __shared__ float red[2 * COUT];
    __shared__ float sc2[COUT], sh2[COUT];

    int t = threadIdx.x, lane = t & 31, w = t >> 5;
    int wrow = w & 3, wcol = w >> 2;
    int g = lane >> 2, tg = lane & 3;

    if (t < COUT) {
        bsh[t] = bf[t];
        int conv = t >> 6, c = t & 63;
        float mu  = g_stats[conv * 4 * HH + 2 * HH + c] * (1.f / (float)MM);
        float var = g_stats[conv * 4 * HH + 3 * HH + c] * (1.f / (float)MM) - mu * mu;
        float gv  = conv ? g2b[c] : g2a[c];
        float bev = conv ? be2b[c] : be2a[c];
        float inv = rsqrtf(var + GCU_EPS) * gv;
        sc2[t] = inv;
        sh2[t] = bev - mu * inv;
    }
    red[t] = 0.f;

    for (int i = 0; i < 16; i++) {
        int set  = w * 16 + i;
        int swc  = set >> 6, snb = (set >> 3) & 7, skb = set & 7;
        int o    = swc * 64 + snb * 8 + g;
        int k0   = skb * 16 + tg * 2;
        const float* Wr = Wf + o * COUT + k0;
        uint32_t h0, l0, h1, l1;
        split2(Wr[0], Wr[1], h0, l0);
        split2(Wr[8], Wr[9], h1, l1);
        int bidx = (((swc * 8 + snb) * 8 + skb) * 32 + lane) * 2;
        sWhi[bidx]      = h0;  sWhi[bidx + 1]  = h1;
        sWloF[bidx]     = l0;  sWloF[bidx + 1] = l1;
    }
    __syncthreads();

    int nbase = blockIdx.x * 128;
    for (int idx = t; idx < 128 * 64; idx += 256) {
        int r = idx >> 6, pp = idx & 63;
        int chunk = pp >> 5, p = pp & 31;
        int n = nbase + r;
        float vx = 0.f, vy = 0.f;
        if (n < NN) {
            uint2 mv = *(const uint2*)&g_nodemax[(size_t)chunk * NN * HH + n * HH + 2 * p];
            int ch = chunk * 64 + 2 * p;
            vx = __uint_as_float(mv.x & 0x7fffffffu) * sc2[ch]     + sh2[ch];
            vy = __uint_as_float(mv.y & 0x7fffffffu) * sc2[ch + 1] + sh2[ch + 1];
        }
        uint32_t hiw, low;
        split2(vx, vy, hiw, low);
        int off = chunk * 16384 + r * 128 + ((p * 4) ^ ((r & 7) << 4));
        *(uint32_t*)(sXhi + off) = hiw;
        *(uint32_t*)(sXlo + off) = low;
    }
    __syncthreads();

    float acc[2][8][4];
#pragma unroll
    for (int mb = 0; mb < 2; mb++)
#pragma unroll
        for (int nb = 0; nb < 8; nb++)
#pragma unroll
            for (int j = 0; j < 4; j++) acc[mb][nb][j] = 0.f;

    uint32_t xHiBase = smem_u32(sXhi), xLoBase = smem_u32(sXlo);
    int sub = lane >> 3, rr = lane & 7;
#pragma unroll
    for (int kb = 0; kb < 8; kb++) {
        int chunk = kb >> 2, kk = kb & 3;
        uint32_t ahi[2][4], alo[2][4];
#pragma unroll
        for (int mb = 0; mb < 2; mb++) {
            int r    = wrow * 32 + mb * 16 + (sub & 1) * 8 + rr;
            int colb = kk * 32 + (sub >> 1) * 16;
            uint32_t a = (uint32_t)(chunk * 16384 + r * 128 + (colb ^ ((r & 7) << 4)));
            ldm_x4(ahi[mb], xHiBase + a);
            ldm_x4(alo[mb], xLoBase + a);
        }
#pragma unroll
        for (int nb = 0; nb < 8; nb++) {
            int bidx = (((wcol * 8 + nb) * 8 + kb) * 32 + lane) * 2;
            uint2 wh = *(const uint2*)&sWhi[bidx];
            uint2 wl = *(const uint2*)&sWloF[bidx];
            uint32_t whi2[2] = { wh.x, wh.y };
            uint32_t wlo2[2] = { wl.x, wl.y };
#pragma unroll
            for (int mb = 0; mb < 2; mb++) {
                mma16816(acc[mb][nb], ahi[mb], whi2);
                mma16816(acc[mb][nb], alo[mb], whi2);
                mma16816(acc[mb][nb], ahi[mb], wlo2);
            }
        }
    }

    float ls[16], lq[16];
#pragma unroll
    for (int i = 0; i < 16; i++) { ls[i] = 0.f; lq[i] = 0.f; }
#pragma unroll
    for (int mb = 0; mb < 2; mb++) {
#pragma unroll
        for (int half = 0; half < 2; half++) {
            int n = nbase + wrow * 32 + mb * 16 + half * 8 + g;
            if (n >= NN) continue;
#pragma unroll
            for (int nb = 0; nb < 8; nb++) {
                int o = wcol * 64 + nb * 8 + tg * 2;
                float v0 = fmaxf(acc[mb][nb][half * 2]     + bsh[o],     0.f);
                float v1 = fmaxf(acc[mb][nb][half * 2 + 1] + bsh[o + 1], 0.f);
                out[n * COUT + o]     = v0;
                out[n * COUT + o + 1] = v1;
                ls[nb * 2]     += v0; lq[nb * 2]     += v0 * v0;
                ls[nb * 2 + 1] += v1; lq[nb * 2 + 1] += v1 * v1;
            }
        }
    }
#pragma unroll
    for (int i = 0; i < 16; i++) {
#pragma unroll
        for (int dlt = 16; dlt >= 4; dlt >>= 1) {
            ls[i] += __shfl_down_sync(0xffffffffu, ls[i], dlt);
            lq[i] += __shfl_down_sync(0xffffffffu, lq[i], dlt);
        }
    }
    if (lane < 4) {
#pragma unroll
        for (int nb = 0; nb < 8; nb++) {
            int o = wcol * 64 + nb * 8 + tg * 2;
            atomicAdd(&red[o],            ls[nb * 2]);
            atomicAdd(&red[o + 1],        ls[nb * 2 + 1]);
            atomicAdd(&red[COUT + o],     lq[nb * 2]);
            atomicAdd(&red[COUT + o + 1], lq[nb * 2 + 1]);
        }
    }
    __syncthreads();
    if (t < COUT) {
        atomicAdd(&g_fstats[t],        red[t]);
        atomicAdd(&g_fstats[COUT + t], red[COUT + t]);
    }
}

// ---------------------------------------------------------------------------
__global__ __launch_bounds__(256) void k_norm(const float* __restrict__ gf,
                                              const float* __restrict__ bef,
                                              float* __restrict__ out) {
    __shared__ float sc[COUT], sh[COUT];
    int t = threadIdx.x;
    if (t < COUT) {
        float mu  = g_fstats[t] * (1.f / (float)NN);
        float var = g_fstats[COUT + t] * (1.f / (float)NN) - mu * mu;
        float inv = rsqrtf(var + GCU_EPS) * gf[t];
        sc[t] = inv;
        sh[t] = bef[t] - mu * inv;
    }
    __syncthreads();
    int i = blockIdx.x * 256 + t, st = gridDim.x * 256;
    for (; i < NN * COUT; i += st) {
        int c = i & 127;
        out[i] = out[i] * sc[c] + sh[c];
    }
}

// ---------------------------------------------------------------------------
extern "C" void kernel_launch(void* const* d_in, const int* in_sizes, int n_in,
                              void* d_out, int out_size) {
    const float* x     = (const float*)d_in[0];
    const int*   tpl_e = (const int*)d_in[1];
    const int*   geo_e = (const int*)d_in[2];
    const float* prm[2][8];
    for (int c = 0; c < 2; c++)
        for (int k = 0; k < 8; k++)
            prm[c][k] = (const float*)d_in[3 + c * 8 + k];
    const float* mlp_W  = (const float*)d_in[19];
    const float* mlp_b  = (const float*)d_in[20];
    const float* mlp_g  = (const float*)d_in[21];
    const float* mlp_be = (const float*)d_in[22];
    float* out = (float*)d_out;

    static int attr_done = 0;
    if (!attr_done) {
        cudaFuncSetAttribute(k_final_gemm_mma,
                             cudaFuncAttributeMaxDynamicSharedMemorySize, FG_SMEM);
        cudaFuncSetAttribute(k_edge_gemm_mma,
                             cudaFuncAttributeMaxDynamicSharedMemorySize, EG_SMEM);
        attr_done = 1;
    }

    k_clear<<<2048, 256>>>();
    k_hist_count<<<2048, 256>>>(tpl_e + EE, geo_e + EE);
    k_alloc<<<dim3((NN + 255) / 256, 2), 256>>>();
    k_scatter<<<2048, 256>>>(tpl_e, tpl_e + EE, geo_e, geo_e + EE);
    k_precompute2<<<2048, 256>>>(x, prm[0][0], prm[0][1], prm[1][0], prm[1][1]);
    k_edge_stats<<<dim3(1024, 2), 256>>>();
    k_edge_gemm_mma<<<dim3(444, 2), 256, EG_SMEM>>>(
        prm[0][4], prm[0][5], prm[0][2], prm[0][3],
        prm[1][4], prm[1][5], prm[1][2], prm[1][3]);
    k_final_gemm_mma<<<(NN + 127) / 128, 256, FG_SMEM>>>(
        mlp_W, mlp_b, prm[0][6], prm[0][7], prm[1][6], prm[1][7], out);
    k_norm<<<2048, 256>>>(mlp_g, mlp_be, out);
}